// round 1
// baseline (speedup 1.0000x reference)
#include <cuda_runtime.h>
#include <math.h>

#define BB 256
#define SS 8192
#define FF 2048
#define KNB 20

// ---------------- scratch ----------------
static __device__ float g_x [BB * FF];   // normalized inputs0
static __device__ float g_C [BB * SS];   // gemm outputs (scores / TEMP)
static __device__ float g_E0[BB * SS];   // exp(l0 - m0)
static __device__ float g_E1[BB * SS];   // exp(l1 - m1)
static __device__ float g_m [2 * BB];    // row max   (0: logits0, 1: logits1)
static __device__ float g_Z [2 * BB];    // row sumexp
static __device__ float g_acc[3];        // nce_sum, ce_sum, kl_sum

// ---------------- reductions (broadcast result to all threads) --------------
__device__ __forceinline__ float bsum(float v) {
    __shared__ float sh[33];
    int lane = threadIdx.x & 31, w = threadIdx.x >> 5, nw = (blockDim.x + 31) >> 5;
    #pragma unroll
    for (int o = 16; o; o >>= 1) v += __shfl_xor_sync(0xffffffffu, v, o);
    if (lane == 0) sh[w] = v;
    __syncthreads();
    v = (threadIdx.x < nw) ? sh[threadIdx.x] : 0.f;
    if (w == 0) {
        #pragma unroll
        for (int o = 16; o; o >>= 1) v += __shfl_xor_sync(0xffffffffu, v, o);
        if (lane == 0) sh[32] = v;
    }
    __syncthreads();
    v = sh[32];
    __syncthreads();
    return v;
}

__device__ __forceinline__ float bmax(float v) {
    __shared__ float sh[33];
    int lane = threadIdx.x & 31, w = threadIdx.x >> 5, nw = (blockDim.x + 31) >> 5;
    #pragma unroll
    for (int o = 16; o; o >>= 1) v = fmaxf(v, __shfl_xor_sync(0xffffffffu, v, o));
    if (lane == 0) sh[w] = v;
    __syncthreads();
    v = (threadIdx.x < nw) ? sh[threadIdx.x] : -1e30f;
    if (w == 0) {
        #pragma unroll
        for (int o = 16; o; o >>= 1) v = fmaxf(v, __shfl_xor_sync(0xffffffffu, v, o));
        if (lane == 0) sh[32] = v;
    }
    __syncthreads();
    v = sh[32];
    __syncthreads();
    return v;
}

// ---------------- kernels ----------------
__global__ void k_zero() { if (threadIdx.x < 3) g_acc[threadIdx.x] = 0.f; }

// normalize inputs0 rows -> g_x. grid=BB, block=256
__global__ void k_norm(const float* __restrict__ in) {
    int b = blockIdx.x, t = threadIdx.x;
    const float4* r = (const float4*)(in + (size_t)b * FF);
    float4 v0 = r[t], v1 = r[t + 256];
    float s = v0.x*v0.x + v0.y*v0.y + v0.z*v0.z + v0.w*v0.w
            + v1.x*v1.x + v1.y*v1.y + v1.z*v1.z + v1.w*v1.w;
    s = bsum(s);
    float inv = 1.f / fmaxf(sqrtf(s), 1e-12f);
    v0.x *= inv; v0.y *= inv; v0.z *= inv; v0.w *= inv;
    v1.x *= inv; v1.y *= inv; v1.z *= inv; v1.w *= inv;
    float4* o = (float4*)(g_x + (size_t)b * FF);
    o[t] = v0; o[t + 256] = v1;
}

// C[m,n] = (1/TEMP) * dot(x[m,:], feat[n,:]).  M=256, N=8192, K=2048.
// BM=64 BN=128 BK=16, 128 threads, 8x8 register tile. grid=(64,4)
__global__ void __launch_bounds__(128) k_gemm(const float* __restrict__ Bmat) {
    const int BM = 64, BN = 128, BK = 16;
    __shared__ float As[BK][BM];
    __shared__ float Bs[BK][BN];
    int bn = blockIdx.x * BN, bm = blockIdx.y * BM;
    int tid = threadIdx.x;
    int lr = tid >> 2, lc = (tid & 3) * 4;   // loader: 32 rows x 4 float4-cols
    int ty = tid >> 4, tx = tid & 15;        // compute: 8 x 16 threads
    float acc[8][8] = {};
    for (int k0 = 0; k0 < FF; k0 += BK) {
        #pragma unroll
        for (int i = 0; i < 2; i++) {
            int r = lr + i * 32;
            float4 a = *(const float4*)(g_x + (size_t)(bm + r) * FF + k0 + lc);
            As[lc + 0][r] = a.x; As[lc + 1][r] = a.y;
            As[lc + 2][r] = a.z; As[lc + 3][r] = a.w;
        }
        #pragma unroll
        for (int i = 0; i < 4; i++) {
            int r = lr + i * 32;
            float4 b = *(const float4*)(Bmat + (size_t)(bn + r) * FF + k0 + lc);
            Bs[lc + 0][r] = b.x; Bs[lc + 1][r] = b.y;
            Bs[lc + 2][r] = b.z; Bs[lc + 3][r] = b.w;
        }
        __syncthreads();
        #pragma unroll
        for (int k = 0; k < BK; k++) {
            float a[8], bb[8];
            #pragma unroll
            for (int i = 0; i < 8; i++) a[i] = As[k][ty * 8 + i];
            #pragma unroll
            for (int j = 0; j < 8; j++) bb[j] = Bs[k][tx * 8 + j];
            #pragma unroll
            for (int i = 0; i < 8; i++)
                #pragma unroll
                for (int j = 0; j < 8; j++) acc[i][j] += a[i] * bb[j];
        }
        __syncthreads();
    }
    const float invT = 20.0f;  // 1/0.05
    #pragma unroll
    for (int i = 0; i < 8; i++) {
        float* c = g_C + (size_t)(bm + ty * 8 + i) * SS + bn + tx * 8;
        float4 v0 = { acc[i][0]*invT, acc[i][1]*invT, acc[i][2]*invT, acc[i][3]*invT };
        float4 v1 = { acc[i][4]*invT, acc[i][5]*invT, acc[i][6]*invT, acc[i][7]*invT };
        *(float4*)(c)     = v0;
        *(float4*)(c + 4) = v1;
    }
}

// loss_nce partial: (m + log Z) - C[b, target[b]].  grid=BB, block=256
__global__ void k_nce(const int* __restrict__ targets) {
    int b = blockIdx.x, t = threadIdx.x;
    const float* row = g_C + (size_t)b * SS;
    float m = -1e30f;
    for (int s = t; s < SS; s += 256) m = fmaxf(m, row[s]);
    m = bmax(m);
    float z = 0.f;
    for (int s = t; s < SS; s += 256) z += expf(row[s] - m);
    z = bsum(z);
    if (t == 0) atomicAdd(&g_acc[0], (m + logf(z)) - row[targets[b]]);
}

// per-row max/sumexp + E = exp(l - m) for both logit tensors. grid=(BB,2), block=256
__global__ void k_stats(const float* __restrict__ l0, const float* __restrict__ l1) {
    int b = blockIdx.x, which = blockIdx.y, t = threadIdx.x;
    const float* L = which ? l1 : l0;
    float* E = which ? g_E1 : g_E0;
    const float* row = L + (size_t)b * SS;
    float m = -1e30f;
    for (int s = t; s < SS; s += 256) m = fmaxf(m, row[s]);
    m = bmax(m);
    float z = 0.f;
    float* er = E + (size_t)b * SS;
    for (int s = t; s < SS; s += 256) {
        float e = expf(row[s] - m);
        er[s] = e;
        z += e;
    }
    z = bsum(z);
    if (t == 0) { g_m[which * BB + b] = m; g_Z[which * BB + b] = z; }
}

// neighbor-mixed CE + KL terms. grid=BB, block=256
__global__ void k_neigh(const float* __restrict__ l0, const float* __restrict__ l1,
                        const int* __restrict__ targets,
                        const int* __restrict__ neighbors,
                        const float* __restrict__ ndist) {
    int b = blockIdx.x, t = threadIdx.x;
    __shared__ int   nk[KNB];
    __shared__ float c0[KNB], c1[KNB], uu[KNB], ew[KNB];
    __shared__ float ssum;
    if (t < KNB) {
        nk[t] = neighbors[b * KNB + t];
        ew[t] = expf(ndist[b * KNB + t] * (1.0f / 0.6f));
    }
    __syncthreads();
    if (t == 0) { float s = 0.f; for (int k = 0; k < KNB; k++) s += ew[k]; ssum = s; }
    __syncthreads();
    if (t < KNB) {
        // duplicated-distance softmax over 2K entries -> pair weight e_k/(2*sum)
        float w = ew[t] / (2.0f * ssum);
        int n = nk[t];
        c0[t] = w / g_Z[n];            // weight * softmax0 normalizer
        c1[t] = w / g_Z[BB + n];       // weight * softmax1 normalizer
        uu[t] = 1.0f / ((float)KNB * g_Z[n]);  // KL-branch mean of softmax0
    }
    __syncthreads();
    float lZ0 = g_m[b]      + logf(g_Z[b]);
    float lZ1 = g_m[BB + b] + logf(g_Z[BB + b]);
    float aCe = 0.f, aKl = 0.f;
    for (int s = t; s < SS; s += 256) {
        float ln1 = 0.f, tt = 0.f;
        #pragma unroll
        for (int k = 0; k < KNB; k++) {
            int n = nk[k];
            float e0 = g_E0[(size_t)n * SS + s];
            float e1 = g_E1[(size_t)n * SS + s];
            ln1 += c0[k] * e0 + c1[k] * e1;
            tt  += uu[k] * e0;
        }
        float lp0 = l0[(size_t)b * SS + s] - lZ0;
        float lp1 = l1[(size_t)b * SS + s] - lZ1;
        aCe += ln1 * lp0;
        aKl += tt * (logf(fmaxf(tt, 1e-12f)) - lp1);
    }
    aCe = bsum(aCe);
    aKl = bsum(aKl);
    if (t == 0) {
        float lp0t = l0[(size_t)b * SS + targets[b]] - lZ0;
        // loss_ce_b = -(alpha*lp0[target] + (1-alpha)*sum_s ln1*lp0)
        atomicAdd(&g_acc[1], -(0.9f * lp0t + 0.1f * aCe));
        atomicAdd(&g_acc[2], aKl);
    }
}

__global__ void k_fin(float* __restrict__ out, const float* __restrict__ ramp) {
    if (threadIdx.x == 0) {
        const float invB = 1.0f / 256.0f;
        out[0] = g_acc[0] * invB;                     // loss_nce
        out[1] = 1.0f * g_acc[1] * invB;              // LAMBDA1 * loss_ce
        out[2] = 1.0f * ramp[0] * g_acc[2] * invB;    // LAMBDA2 * rampup * kl
    }
}

// bulk copy features -> out (out may be misaligned for float4 stores)
__global__ void k_copy(const float* __restrict__ f, float* __restrict__ out) {
    size_t n4 = (size_t)SS * FF / 4;
    for (size_t i = (size_t)blockIdx.x * blockDim.x + threadIdx.x; i < n4;
         i += (size_t)gridDim.x * blockDim.x) {
        float4 v = ((const float4*)f)[i];
        float* o = out + i * 4;
        o[0] = v.x; o[1] = v.y; o[2] = v.z; o[3] = v.w;
    }
}

// momentum update of the 256 targeted rows (last occurrence wins). grid=BB, block=256
__global__ void k_upd(const float* __restrict__ f, const int* __restrict__ targets,
                      float* __restrict__ out) {
    int b = blockIdx.x, t = threadIdx.x;
    __shared__ int flag;
    int tb = targets[b];
    if (t == 0) {
        int ok = 1;
        for (int j = b + 1; j < BB; j++)
            if (targets[j] == tb) { ok = 0; break; }
        flag = ok;
    }
    __syncthreads();
    if (!flag) return;
    const float* fr = f   + (size_t)tb * FF;
    const float* xr = g_x + (size_t)b  * FF;
    float u[8];
    float s = 0.f;
    #pragma unroll
    for (int i = 0; i < 8; i++) {
        float v = 0.2f * fr[t + i * 256] + 0.8f * xr[t + i * 256];
        u[i] = v; s += v * v;
    }
    s = bsum(s);
    float inv = 1.f / fmaxf(sqrtf(s), 1e-12f);
    float* orow = out + (size_t)tb * FF;
    #pragma unroll
    for (int i = 0; i < 8; i++) orow[t + i * 256] = u[i] * inv;
}

extern "C" void kernel_launch(void* const* d_in, const int* in_sizes, int n_in,
                              void* d_out, int out_size) {
    const float* inputs0   = (const float*)d_in[0];
    const float* l0        = (const float*)d_in[1];
    const float* l1        = (const float*)d_in[2];
    const int*   targets   = (const int*)d_in[3];
    // d_in[4] = indexes (identity; unused)
    const int*   neighbors = (const int*)d_in[5];
    const float* ndist     = (const float*)d_in[6];
    const float* ramp      = (const float*)d_in[7];
    const float* feat      = (const float*)d_in[8];
    float* out = (float*)d_out;

    k_zero<<<1, 32>>>();
    k_norm<<<BB, 256>>>(inputs0);
    dim3 gg(SS / 128, BB / 64);
    k_gemm<<<gg, 128>>>(feat);
    k_nce<<<BB, 256>>>(targets);
    dim3 gs(BB, 2);
    k_stats<<<gs, 256>>>(l0, l1);
    k_neigh<<<BB, 256>>>(l0, l1, targets, neighbors, ndist);
    k_fin<<<1, 32>>>(out, ramp);
    k_copy<<<2048, 256>>>(feat, out + 3);
    k_upd<<<BB, 256>>>(feat, targets, out + 3);
}

// round 6
// speedup vs baseline: 1.6775x; 1.6775x over previous
#include <cuda_runtime.h>
#include <cuda_bf16.h>
#include <math.h>
#include <stdint.h>

#define BB 256
#define SS 8192
#define FF 2048
#define KNB 20

// ---------------- scratch ----------------
static __device__ float g_x [BB * FF];   // normalized inputs0
static __device__ float g_C [BB * SS];   // gemm outputs (scores / TEMP)
static __device__ float g_E0[BB * SS];   // exp(l0 - m0)
static __device__ float g_E1[BB * SS];   // exp(l1 - m1)
static __device__ float g_m [2 * BB];
static __device__ float g_Z [2 * BB];
static __device__ float g_acc[3];

// row-major bf16 hi/lo images
static __device__ __align__(16) __nv_bfloat16 g_Ah[BB * FF];
static __device__ __align__(16) __nv_bfloat16 g_Al[BB * FF];
static __device__ __align__(16) __nv_bfloat16 g_Bh[SS * FF];
static __device__ __align__(16) __nv_bfloat16 g_Bl[SS * FF];

// ---------------- helpers ----------------
__device__ __forceinline__ uint32_t smem_u32(const void* p) {
    uint32_t a;
    asm("{ .reg .u64 t; cvta.to.shared.u64 t, %1; cvt.u32.u64 %0, t; }" : "=r"(a) : "l"(p));
    return a;
}
__device__ __forceinline__ void cp16(uint32_t d, const void* s) {
    asm volatile("cp.async.cg.shared.global [%0], [%1], 16;" :: "r"(d), "l"(s));
}
__device__ __forceinline__ void cp_commit() {
    asm volatile("cp.async.commit_group;" ::: "memory");
}
__device__ __forceinline__ void cp_wait2() {
    asm volatile("cp.async.wait_group 2;" ::: "memory");
}
__device__ __forceinline__ void ldsm4(uint32_t* r, uint32_t a) {
    asm volatile("ldmatrix.sync.aligned.m8n8.x4.shared.b16 {%0,%1,%2,%3}, [%4];"
                 : "=r"(r[0]), "=r"(r[1]), "=r"(r[2]), "=r"(r[3]) : "r"(a));
}
__device__ __forceinline__ void mma16816(float* c, const uint32_t* a, uint32_t b0, uint32_t b1) {
    asm volatile("mma.sync.aligned.m16n8k16.row.col.f32.bf16.bf16.f32 "
                 "{%0,%1,%2,%3},{%4,%5,%6,%7},{%8,%9},{%0,%1,%2,%3};"
                 : "+f"(c[0]), "+f"(c[1]), "+f"(c[2]), "+f"(c[3])
                 : "r"(a[0]), "r"(a[1]), "r"(a[2]), "r"(a[3]), "r"(b0), "r"(b1));
}

// ---------------- reductions ----------------
__device__ __forceinline__ float bsum(float v) {
    __shared__ float sh[33];
    int lane = threadIdx.x & 31, w = threadIdx.x >> 5, nw = (blockDim.x + 31) >> 5;
    #pragma unroll
    for (int o = 16; o; o >>= 1) v += __shfl_xor_sync(0xffffffffu, v, o);
    if (lane == 0) sh[w] = v;
    __syncthreads();
    v = (threadIdx.x < nw) ? sh[threadIdx.x] : 0.f;
    if (w == 0) {
        #pragma unroll
        for (int o = 16; o; o >>= 1) v += __shfl_xor_sync(0xffffffffu, v, o);
        if (lane == 0) sh[32] = v;
    }
    __syncthreads();
    v = sh[32];
    __syncthreads();
    return v;
}
__device__ __forceinline__ float bmax(float v) {
    __shared__ float sh[33];
    int lane = threadIdx.x & 31, w = threadIdx.x >> 5, nw = (blockDim.x + 31) >> 5;
    #pragma unroll
    for (int o = 16; o; o >>= 1) v = fmaxf(v, __shfl_xor_sync(0xffffffffu, v, o));
    if (lane == 0) sh[w] = v;
    __syncthreads();
    v = (threadIdx.x < nw) ? sh[threadIdx.x] : -1e30f;
    if (w == 0) {
        #pragma unroll
        for (int o = 16; o; o >>= 1) v = fmaxf(v, __shfl_xor_sync(0xffffffffu, v, o));
        if (lane == 0) sh[32] = v;
    }
    __syncthreads();
    v = sh[32];
    __syncthreads();
    return v;
}

// ---------------- kernels ----------------
__global__ void k_zero() { if (threadIdx.x < 3) g_acc[threadIdx.x] = 0.f; }

__device__ __forceinline__ void split8(const float* v, unsigned short* h, unsigned short* l) {
    #pragma unroll
    for (int i = 0; i < 8; i++) {
        __nv_bfloat16 hb = __float2bfloat16(v[i]);
        float hf = __bfloat162float(hb);
        __nv_bfloat16 lb = __float2bfloat16(v[i] - hf);
        h[i] = __bfloat16_as_ushort(hb);
        l[i] = __bfloat16_as_ushort(lb);
    }
}

// normalize inputs0 -> g_x + bf16 hi/lo rows. grid=BB, block=256
__global__ void k_norm(const float* __restrict__ in) {
    int b = blockIdx.x, t = threadIdx.x;
    const float4* r = (const float4*)(in + (size_t)b * FF);
    float4 v0 = r[2 * t], v1 = r[2 * t + 1];
    float s = v0.x*v0.x + v0.y*v0.y + v0.z*v0.z + v0.w*v0.w
            + v1.x*v1.x + v1.y*v1.y + v1.z*v1.z + v1.w*v1.w;
    s = bsum(s);
    float inv = 1.f / fmaxf(sqrtf(s), 1e-12f);
    v0.x *= inv; v0.y *= inv; v0.z *= inv; v0.w *= inv;
    v1.x *= inv; v1.y *= inv; v1.z *= inv; v1.w *= inv;
    float4* o = (float4*)(g_x + (size_t)b * FF);
    o[2 * t] = v0; o[2 * t + 1] = v1;
    float v[8] = { v0.x, v0.y, v0.z, v0.w, v1.x, v1.y, v1.z, v1.w };
    __align__(16) unsigned short h[8], lo[8];
    split8(v, h, lo);
    size_t e = (size_t)b * FF + 8 * t;
    *(uint4*)(g_Ah + e) = *(uint4*)h;
    *(uint4*)(g_Al + e) = *(uint4*)lo;
}

// features -> bf16 hi/lo rows. grid=SS, block=256
__global__ void k_convB(const float* __restrict__ f) {
    int n = blockIdx.x, t = threadIdx.x;
    const float4* r = (const float4*)(f + (size_t)n * FF);
    float4 v0 = r[2 * t], v1 = r[2 * t + 1];
    float v[8] = { v0.x, v0.y, v0.z, v0.w, v1.x, v1.y, v1.z, v1.w };
    __align__(16) unsigned short h[8], lo[8];
    split8(v, h, lo);
    size_t e = (size_t)n * FF + 8 * t;
    *(uint4*)(g_Bh + e) = *(uint4*)h;
    *(uint4*)(g_Bl + e) = *(uint4*)lo;
}

// ---------------- tensor-core GEMM (mma.sync bf16 split) ----------------
// C[256,8192] = 20 * x @ feat^T, via Ah*Bh + Ah*Bl + Al*Bh over K chunks of 32.
// grid=(64,2) CTAs of 128x128; 256 threads; 4-stage cp.async pipeline.
#define STRIDE 40                       // smem row stride in bf16 elems (80 B)
#define TILE_BYTES (128 * STRIDE * 2)   // 10240
#define CHUNK_BYTES (2 * TILE_BYTES)    // 20480 (A tile + B tile)
#define NCHUNK 192                      // 3 passes x 64 k-chunks

__device__ __forceinline__ void gemm_issue(int c, int bm, int bn, int tid, uint32_t sb) {
    if (c < NCHUNK) {
        int pass = c >> 6, kc = c & 63;
        const __nv_bfloat16* A  = (pass == 2) ? g_Al : g_Ah;
        const __nv_bfloat16* Bm = (pass == 1) ? g_Bl : g_Bh;
        uint32_t st = sb + (c & 3) * CHUNK_BYTES;
        #pragma unroll
        for (int i = 0; i < 2; i++) {
            int q = tid + i * 256;
            int row = q >> 2, qc = q & 3;
            cp16(st + row * (STRIDE * 2) + qc * 16,
                 (const char*)(A + (size_t)(bm + row) * FF + kc * 32) + qc * 16);
            cp16(st + TILE_BYTES + row * (STRIDE * 2) + qc * 16,
                 (const char*)(Bm + (size_t)(bn + row) * FF + kc * 32) + qc * 16);
        }
    }
    cp_commit();
}

__global__ void __launch_bounds__(256) k_gemm_mma() {
    extern __shared__ __align__(128) unsigned char smem[];
    uint32_t sb = smem_u32(smem);
    int tid = threadIdx.x;
    int bn = blockIdx.x * 128, bm = blockIdx.y * 128;
    int wid = tid >> 5, lane = tid & 31;
    int wm = (wid >> 2) * 64, wn = (wid & 3) * 32;
    int mi = lane >> 3, lr = lane & 7;
    // ldmatrix lane element offsets
    uint32_t aoff = (uint32_t)(((wm + lr + (mi & 1) * 8) * STRIDE + (mi >> 1) * 8) * 2);
    uint32_t boff = (uint32_t)(((wn + lr + (mi >> 1) * 8) * STRIDE + (mi & 1) * 8) * 2);

    float acc[4][4][4];
    #pragma unroll
    for (int i = 0; i < 4; i++)
        #pragma unroll
        for (int j = 0; j < 4; j++)
            #pragma unroll
            for (int q = 0; q < 4; q++) acc[i][j][q] = 0.f;

    gemm_issue(0, bm, bn, tid, sb);
    gemm_issue(1, bm, bn, tid, sb);
    gemm_issue(2, bm, bn, tid, sb);

    for (int c = 0; c < NCHUNK; c++) {
        cp_wait2();
        __syncthreads();
        gemm_issue(c + 3, bm, bn, tid, sb);
        uint32_t st = sb + (c & 3) * CHUNK_BYTES;
        #pragma unroll
        for (int ks = 0; ks < 2; ks++) {
            uint32_t a[4][4], b[2][4];
            #pragma unroll
            for (int i = 0; i < 4; i++)
                ldsm4(a[i], st + aoff + (i * 16 * STRIDE + ks * 16) * 2);
            #pragma unroll
            for (int j = 0; j < 2; j++)
                ldsm4(b[j], st + TILE_BYTES + boff + (j * 16 * STRIDE + ks * 16) * 2);
            #pragma unroll
            for (int i = 0; i < 4; i++)
                #pragma unroll
                for (int j = 0; j < 4; j++)
                    mma16816(acc[i][j], a[i], b[j >> 1][(j & 1) * 2], b[j >> 1][(j & 1) * 2 + 1]);
        }
    }

    // epilogue: scale by 1/TEMP = 20 and store fp32
    #pragma unroll
    for (int i = 0; i < 4; i++) {
        int r0 = bm + wm + i * 16 + (lane >> 2);
        #pragma unroll
        for (int j = 0; j < 4; j++) {
            int col = bn + wn + j * 8 + (lane & 3) * 2;
            float2 v0 = { acc[i][j][0] * 20.f, acc[i][j][1] * 20.f };
            float2 v1 = { acc[i][j][2] * 20.f, acc[i][j][3] * 20.f };
            *(float2*)(g_C + (size_t)r0 * SS + col)       = v0;
            *(float2*)(g_C + (size_t)(r0 + 8) * SS + col) = v1;
        }
    }
}

// loss_nce partial. grid=BB, block=256
__global__ void k_nce(const int* __restrict__ targets) {
    int b = blockIdx.x, t = threadIdx.x;
    const float* row = g_C + (size_t)b * SS;
    float m = -1e30f;
    for (int s = t; s < SS; s += 256) m = fmaxf(m, row[s]);
    m = bmax(m);
    float z = 0.f;
    for (int s = t; s < SS; s += 256) z += expf(row[s] - m);
    z = bsum(z);
    if (t == 0) atomicAdd(&g_acc[0], (m + logf(z)) - row[targets[b]]);
}

// per-row max/sumexp + E = exp(l - m). grid=(BB,2), block=256
__global__ void k_stats(const float* __restrict__ l0, const float* __restrict__ l1) {
    int b = blockIdx.x, which = blockIdx.y, t = threadIdx.x;
    const float* L = which ? l1 : l0;
    float* E = which ? g_E1 : g_E0;
    const float* row = L + (size_t)b * SS;
    float m = -1e30f;
    for (int s = t; s < SS; s += 256) m = fmaxf(m, row[s]);
    m = bmax(m);
    float z = 0.f;
    float* er = E + (size_t)b * SS;
    for (int s = t; s < SS; s += 256) {
        float e = expf(row[s] - m);
        er[s] = e;
        z += e;
    }
    z = bsum(z);
    if (t == 0) { g_m[which * BB + b] = m; g_Z[which * BB + b] = z; }
}

// neighbor-mixed CE + KL. grid=BB, block=256
__global__ void k_neigh(const float* __restrict__ l0, const float* __restrict__ l1,
                        const int* __restrict__ targets,
                        const int* __restrict__ neighbors,
                        const float* __restrict__ ndist) {
    int b = blockIdx.x, t = threadIdx.x;
    __shared__ int   nk[KNB];
    __shared__ float c0[KNB], c1[KNB], uu[KNB], ew[KNB];
    __shared__ float ssum;
    if (t < KNB) {
        nk[t] = neighbors[b * KNB + t];
        ew[t] = expf(ndist[b * KNB + t] * (1.0f / 0.6f));
    }
    __syncthreads();
    if (t == 0) { float s = 0.f; for (int k = 0; k < KNB; k++) s += ew[k]; ssum = s; }
    __syncthreads();
    if (t < KNB) {
        float w = ew[t] / (2.0f * ssum);
        int n = nk[t];
        c0[t] = w / g_Z[n];
        c1[t] = w / g_Z[BB + n];
        uu[t] = 1.0f / ((float)KNB * g_Z[n]);
    }
    __syncthreads();
    float lZ0 = g_m[b]      + logf(g_Z[b]);
    float lZ1 = g_m[BB + b] + logf(g_Z[BB + b]);
    float aCe = 0.f, aKl = 0.f;
    for (int s = t; s < SS; s += 256) {
        float ln1 = 0.f, tt = 0.f;
        #pragma unroll
        for (int k = 0; k < KNB; k++) {
            int n = nk[k];
            float e0 = g_E0[(size_t)n * SS + s];
            float e1 = g_E1[(size_t)n * SS + s];
            ln1 += c0[k] * e0 + c1[k] * e1;
            tt  += uu[k] * e0;
        }
        float lp0 = l0[(size_t)b * SS + s] - lZ0;
        float lp1 = l1[(size_t)b * SS + s] - lZ1;
        aCe += ln1 * lp0;
        aKl += tt * (logf(fmaxf(tt, 1e-12f)) - lp1);
    }
    aCe = bsum(aCe);
    aKl = bsum(aKl);
    if (t == 0) {
        float lp0t = l0[(size_t)b * SS + targets[b]] - lZ0;
        atomicAdd(&g_acc[1], -(0.9f * lp0t + 0.1f * aCe));
        atomicAdd(&g_acc[2], aKl);
    }
}

__global__ void k_fin(float* __restrict__ out, const float* __restrict__ ramp) {
    if (threadIdx.x == 0) {
        const float invB = 1.0f / 256.0f;
        out[0] = g_acc[0] * invB;
        out[1] = g_acc[1] * invB;
        out[2] = ramp[0] * g_acc[2] * invB;
    }
}

__global__ void k_copy(const float* __restrict__ f, float* __restrict__ out) {
    size_t n4 = (size_t)SS * FF / 4;
    for (size_t i = (size_t)blockIdx.x * blockDim.x + threadIdx.x; i < n4;
         i += (size_t)gridDim.x * blockDim.x) {
        float4 v = ((const float4*)f)[i];
        float* o = out + i * 4;
        o[0] = v.x; o[1] = v.y; o[2] = v.z; o[3] = v.w;
    }
}

__global__ void k_upd(const float* __restrict__ f, const int* __restrict__ targets,
                      float* __restrict__ out) {
    int b = blockIdx.x, t = threadIdx.x;
    __shared__ int flag;
    int tb = targets[b];
    if (t == 0) {
        int ok = 1;
        for (int j = b + 1; j < BB; j++)
            if (targets[j] == tb) { ok = 0; break; }
        flag = ok;
    }
    __syncthreads();
    if (!flag) return;
    const float* fr = f   + (size_t)tb * FF;
    const float* xr = g_x + (size_t)b  * FF;
    float u[8];
    float s = 0.f;
    #pragma unroll
    for (int i = 0; i < 8; i++) {
        float v = 0.2f * fr[t + i * 256] + 0.8f * xr[t + i * 256];
        u[i] = v; s += v * v;
    }
    s = bsum(s);
    float inv = 1.f / fmaxf(sqrtf(s), 1e-12f);
    float* orow = out + (size_t)tb * FF;
    #pragma unroll
    for (int i = 0; i < 8; i++) orow[t + i * 256] = u[i] * inv;
}

extern "C" void kernel_launch(void* const* d_in, const int* in_sizes, int n_in,
                              void* d_out, int out_size) {
    const float* inputs0   = (const float*)d_in[0];
    const float* l0        = (const float*)d_in[1];
    const float* l1        = (const float*)d_in[2];
    const int*   targets   = (const int*)d_in[3];
    const int*   neighbors = (const int*)d_in[5];
    const float* ndist     = (const float*)d_in[6];
    const float* ramp      = (const float*)d_in[7];
    const float* feat      = (const float*)d_in[8];
    float* out = (float*)d_out;

    static int inited = 0;
    if (!inited) {
        cudaFuncSetAttribute(k_gemm_mma, cudaFuncAttributeMaxDynamicSharedMemorySize,
                             4 * CHUNK_BYTES);
        inited = 1;
    }

    k_zero<<<1, 32>>>();
    k_norm<<<BB, 256>>>(inputs0);
    k_convB<<<SS, 256>>>(feat);
    dim3 gg(SS / 128, BB / 128);
    k_gemm_mma<<<gg, 256, 4 * CHUNK_BYTES>>>();
    k_nce<<<BB, 256>>>(targets);
    dim3 gs(BB, 2);
    k_stats<<<gs, 256>>>(l0, l1);
    k_neigh<<<BB, 256>>>(l0, l1, targets, neighbors, ndist);
    k_fin<<<1, 32>>>(out, ramp);
    k_copy<<<2048, 256>>>(feat, out + 3);
    k_upd<<<BB, 256>>>(feat, targets, out + 3);
}

// round 8
// speedup vs baseline: 2.1756x; 1.2969x over previous
#include <cuda_runtime.h>
#include <cuda_bf16.h>
#include <math.h>
#include <stdint.h>

#define BB 256
#define SS 8192
#define FF 2048
#define KNB 20

// ---------------- scratch ----------------
static __device__ float g_x [BB * FF];   // normalized inputs0
static __device__ float g_E0[BB * SS];   // exp(l0 - m0)
static __device__ float g_E1[BB * SS];   // exp(l1 - m1)
static __device__ float g_m [2 * BB];
static __device__ float g_Z [2 * BB];
static __device__ float g_Zn[BB];        // NCE row sum of exp(score - 20)
static __device__ float g_acc[3];

// row-major bf16 images
static __device__ __align__(16) __nv_bfloat16 g_Ah[BB * FF];
static __device__ __align__(16) __nv_bfloat16 g_Bh[SS * FF];

// ---------------- helpers ----------------
__device__ __forceinline__ uint32_t smem_u32(const void* p) {
    uint32_t a;
    asm("{ .reg .u64 t; cvta.to.shared.u64 t, %1; cvt.u32.u64 %0, t; }" : "=r"(a) : "l"(p));
    return a;
}
__device__ __forceinline__ void cp16(uint32_t d, const void* s) {
    asm volatile("cp.async.cg.shared.global [%0], [%1], 16;" :: "r"(d), "l"(s));
}
__device__ __forceinline__ void cp_commit() {
    asm volatile("cp.async.commit_group;" ::: "memory");
}
__device__ __forceinline__ void cp_wait2() {
    asm volatile("cp.async.wait_group 2;" ::: "memory");
}
__device__ __forceinline__ void ldsm4(uint32_t* r, uint32_t a) {
    asm volatile("ldmatrix.sync.aligned.m8n8.x4.shared.b16 {%0,%1,%2,%3}, [%4];"
                 : "=r"(r[0]), "=r"(r[1]), "=r"(r[2]), "=r"(r[3]) : "r"(a));
}
__device__ __forceinline__ void mma16816(float* c, const uint32_t* a, uint32_t b0, uint32_t b1) {
    asm volatile("mma.sync.aligned.m16n8k16.row.col.f32.bf16.bf16.f32 "
                 "{%0,%1,%2,%3},{%4,%5,%6,%7},{%8,%9},{%0,%1,%2,%3};"
                 : "+f"(c[0]), "+f"(c[1]), "+f"(c[2]), "+f"(c[3])
                 : "r"(a[0]), "r"(a[1]), "r"(a[2]), "r"(a[3]), "r"(b0), "r"(b1));
}

// ---------------- reductions ----------------
__device__ __forceinline__ float bsum(float v) {
    __shared__ float sh[33];
    int lane = threadIdx.x & 31, w = threadIdx.x >> 5, nw = (blockDim.x + 31) >> 5;
    #pragma unroll
    for (int o = 16; o; o >>= 1) v += __shfl_xor_sync(0xffffffffu, v, o);
    if (lane == 0) sh[w] = v;
    __syncthreads();
    v = (threadIdx.x < nw) ? sh[threadIdx.x] : 0.f;
    if (w == 0) {
        #pragma unroll
        for (int o = 16; o; o >>= 1) v += __shfl_xor_sync(0xffffffffu, v, o);
        if (lane == 0) sh[32] = v;
    }
    __syncthreads();
    v = sh[32];
    __syncthreads();
    return v;
}
__device__ __forceinline__ float bmax(float v) {
    __shared__ float sh[33];
    int lane = threadIdx.x & 31, w = threadIdx.x >> 5, nw = (blockDim.x + 31) >> 5;
    #pragma unroll
    for (int o = 16; o; o >>= 1) v = fmaxf(v, __shfl_xor_sync(0xffffffffu, v, o));
    if (lane == 0) sh[w] = v;
    __syncthreads();
    v = (threadIdx.x < nw) ? sh[threadIdx.x] : -1e30f;
    if (w == 0) {
        #pragma unroll
        for (int o = 16; o; o >>= 1) v = fmaxf(v, __shfl_xor_sync(0xffffffffu, v, o));
        if (lane == 0) sh[32] = v;
    }
    __syncthreads();
    v = sh[32];
    __syncthreads();
    return v;
}

// ---------------- kernels ----------------
__global__ void k_zero() {
    if (threadIdx.x < 3) g_acc[threadIdx.x] = 0.f;
    g_Zn[threadIdx.x] = 0.f;   // block of 256
}

// normalize inputs0 -> g_x + bf16 rows. grid=BB, block=256
__global__ void k_norm(const float* __restrict__ in) {
    int b = blockIdx.x, t = threadIdx.x;
    const float4* r = (const float4*)(in + (size_t)b * FF);
    float4 v0 = r[2 * t], v1 = r[2 * t + 1];
    float s = v0.x*v0.x + v0.y*v0.y + v0.z*v0.z + v0.w*v0.w
            + v1.x*v1.x + v1.y*v1.y + v1.z*v1.z + v1.w*v1.w;
    s = bsum(s);
    float inv = 1.f / fmaxf(sqrtf(s), 1e-12f);
    v0.x *= inv; v0.y *= inv; v0.z *= inv; v0.w *= inv;
    v1.x *= inv; v1.y *= inv; v1.z *= inv; v1.w *= inv;
    float4* o = (float4*)(g_x + (size_t)b * FF);
    o[2 * t] = v0; o[2 * t + 1] = v1;
    float v[8] = { v0.x, v0.y, v0.z, v0.w, v1.x, v1.y, v1.z, v1.w };
    __align__(16) unsigned short h[8];
    #pragma unroll
    for (int i = 0; i < 8; i++) h[i] = __bfloat16_as_ushort(__float2bfloat16(v[i]));
    *(uint4*)(g_Ah + (size_t)b * FF + 8 * t) = *(uint4*)h;
}

// features -> bf16 rows. grid=SS, block=256
__global__ void k_convB(const float* __restrict__ f) {
    int n = blockIdx.x, t = threadIdx.x;
    const float4* r = (const float4*)(f + (size_t)n * FF);
    float4 v0 = r[2 * t], v1 = r[2 * t + 1];
    float v[8] = { v0.x, v0.y, v0.z, v0.w, v1.x, v1.y, v1.z, v1.w };
    __align__(16) unsigned short h[8];
    #pragma unroll
    for (int i = 0; i < 8; i++) h[i] = __bfloat16_as_ushort(__float2bfloat16(v[i]));
    *(uint4*)(g_Bh + (size_t)n * FF + 8 * t) = *(uint4*)h;
}

// ---------------- tensor-core GEMM fused with NCE partial sums ----------------
// scores[256,8192] = 20 * x @ feat^T (bf16), accumulate sum_s exp(score-20) per row.
// CTA tile 128(M) x 64(N); grid=(128,2); 256 threads; 4-stage cp.async pipeline.
#define STRIDE 40                        // smem row stride in bf16 (80 B)
#define A_TILE_B (128 * STRIDE * 2)      // 10240
#define B_TILE_B (64 * STRIDE * 2)       // 5120
#define STAGE_B  (A_TILE_B + B_TILE_B)   // 15360
#define NCH 64

__device__ __forceinline__ void gemm_issue(int c, int bm, int bn, int tid, uint32_t sb) {
    if (c < NCH) {
        uint32_t st = sb + (c & 3) * STAGE_B;
        #pragma unroll
        for (int i = 0; i < 2; i++) {            // A: 128 rows x 4 x 16B
            int q = tid + i * 256;
            int row = q >> 2, qc = q & 3;
            cp16(st + row * (STRIDE * 2) + qc * 16,
                 (const char*)(g_Ah + (size_t)(bm + row) * FF + c * 32) + qc * 16);
        }
        {                                        // B: 64 rows x 4 x 16B
            int row = tid >> 2, qc = tid & 3;
            cp16(st + A_TILE_B + row * (STRIDE * 2) + qc * 16,
                 (const char*)(g_Bh + (size_t)(bn + row) * FF + c * 32) + qc * 16);
        }
    }
    cp_commit();
}

__global__ void __launch_bounds__(256) k_gemm_mma() {
    extern __shared__ __align__(128) unsigned char smem[];
    uint32_t sb = smem_u32(smem);
    int tid = threadIdx.x;
    int bn = blockIdx.x * 64, bm = blockIdx.y * 128;
    int wid = tid >> 5, lane = tid & 31;
    int wm = (wid >> 1) * 32, wn = (wid & 1) * 32;
    int mi = lane >> 3, lr = lane & 7;
    uint32_t aoff = (uint32_t)(((wm + lr + (mi & 1) * 8) * STRIDE + (mi >> 1) * 8) * 2);
    uint32_t boff = (uint32_t)(A_TILE_B + ((wn + lr + (mi >> 1) * 8) * STRIDE + (mi & 1) * 8) * 2);

    float acc[2][4][4];
    #pragma unroll
    for (int i = 0; i < 2; i++)
        #pragma unroll
        for (int j = 0; j < 4; j++)
            #pragma unroll
            for (int q = 0; q < 4; q++) acc[i][j][q] = 0.f;

    gemm_issue(0, bm, bn, tid, sb);
    gemm_issue(1, bm, bn, tid, sb);
    gemm_issue(2, bm, bn, tid, sb);

    for (int c = 0; c < NCH; c++) {
        cp_wait2();
        __syncthreads();
        gemm_issue(c + 3, bm, bn, tid, sb);
        uint32_t st = sb + (c & 3) * STAGE_B;
        uint32_t a[2][2][4], b[2][2][4];
        #pragma unroll
        for (int ks = 0; ks < 2; ks++) {
            ldsm4(a[ks][0], st + aoff + (0 * 16 * STRIDE + ks * 16) * 2);
            ldsm4(a[ks][1], st + aoff + (1 * 16 * STRIDE + ks * 16) * 2);
            ldsm4(b[ks][0], st + boff + (0 * 16 * STRIDE + ks * 16) * 2);
            ldsm4(b[ks][1], st + boff + (1 * 16 * STRIDE + ks * 16) * 2);
        }
        #pragma unroll
        for (int ks = 0; ks < 2; ks++)
            #pragma unroll
            for (int i = 0; i < 2; i++)
                #pragma unroll
                for (int j = 0; j < 4; j++)
                    mma16816(acc[i][j], a[ks][i],
                             b[ks][j >> 1][(j & 1) * 2], b[ks][j >> 1][(j & 1) * 2 + 1]);
    }

    // fused NCE epilogue: per-row sum of exp(20*acc - 20); no C materialization.
    #pragma unroll
    for (int i = 0; i < 2; i++) {
        float z0 = 0.f, z1 = 0.f;
        #pragma unroll
        for (int j = 0; j < 4; j++) {
            z0 += __expf(fmaf(acc[i][j][0], 20.f, -20.f)) + __expf(fmaf(acc[i][j][1], 20.f, -20.f));
            z1 += __expf(fmaf(acc[i][j][2], 20.f, -20.f)) + __expf(fmaf(acc[i][j][3], 20.f, -20.f));
        }
        z0 += __shfl_xor_sync(0xffffffffu, z0, 1);
        z0 += __shfl_xor_sync(0xffffffffu, z0, 2);
        z1 += __shfl_xor_sync(0xffffffffu, z1, 1);
        z1 += __shfl_xor_sync(0xffffffffu, z1, 2);
        if ((lane & 3) == 0) {
            int r0 = bm + wm + i * 16 + (lane >> 2);
            atomicAdd(&g_Zn[r0], z0);
            atomicAdd(&g_Zn[r0 + 8], z1);
        }
    }
}

// NCE finalize: exact fp32 target score + logsumexp. grid=BB, block=256
__global__ void k_nce2(const int* __restrict__ targets, const float* __restrict__ feat) {
    int b = blockIdx.x, t = threadIdx.x;
    int tb = targets[b];
    const float4* xr = (const float4*)(g_x + (size_t)b * FF);
    const float4* fr = (const float4*)(feat + (size_t)tb * FF);
    float s = 0.f;
    #pragma unroll
    for (int i = 0; i < 2; i++) {
        float4 xv = xr[t + i * 256], fv = fr[t + i * 256];
        s += xv.x * fv.x + xv.y * fv.y + xv.z * fv.z + xv.w * fv.w;
    }
    s = bsum(s);
    if (t == 0) {
        float lse = 20.f + logf(g_Zn[b]);
        atomicAdd(&g_acc[0], lse - 20.f * s);
    }
}

// per-row max/sumexp + E = exp(l - m). grid=(BB,2), block=256
__global__ void k_stats(const float* __restrict__ l0, const float* __restrict__ l1) {
    int b = blockIdx.x, which = blockIdx.y, t = threadIdx.x;
    const float* L = which ? l1 : l0;
    float* E = which ? g_E1 : g_E0;
    const float* row = L + (size_t)b * SS;
    float m = -1e30f;
    for (int s = t; s < SS; s += 256) m = fmaxf(m, row[s]);
    m = bmax(m);
    float z = 0.f;
    float* er = E + (size_t)b * SS;
    for (int s = t; s < SS; s += 256) {
        float e = expf(row[s] - m);
        er[s] = e;
        z += e;
    }
    z = bsum(z);
    if (t == 0) { g_m[which * BB + b] = m; g_Z[which * BB + b] = z; }
}

// neighbor-mixed CE + KL. grid=BB, block=256
__global__ void k_neigh(const float* __restrict__ l0, const float* __restrict__ l1,
                        const int* __restrict__ targets,
                        const int* __restrict__ neighbors,
                        const float* __restrict__ ndist) {
    int b = blockIdx.x, t = threadIdx.x;
    __shared__ int   nk[KNB];
    __shared__ float c0[KNB], c1[KNB], uu[KNB], ew[KNB];
    __shared__ float ssum;
    if (t < KNB) {
        nk[t] = neighbors[b * KNB + t];
        ew[t] = expf(ndist[b * KNB + t] * (1.0f / 0.6f));
    }
    __syncthreads();
    if (t == 0) { float s = 0.f; for (int k = 0; k < KNB; k++) s += ew[k]; ssum = s; }
    __syncthreads();
    if (t < KNB) {
        float w = ew[t] / (2.0f * ssum);
        int n = nk[t];
        c0[t] = w / g_Z[n];
        c1[t] = w / g_Z[BB + n];
        uu[t] = 1.0f / ((float)KNB * g_Z[n]);
    }
    __syncthreads();
    float lZ0 = g_m[b]      + logf(g_Z[b]);
    float lZ1 = g_m[BB + b] + logf(g_Z[BB + b]);
    float aCe = 0.f, aKl = 0.f;
    for (int s = t; s < SS; s += 256) {
        float ln1 = 0.f, tt = 0.f;
        #pragma unroll
        for (int k = 0; k < KNB; k++) {
            int n = nk[k];
            float e0 = g_E0[(size_t)n * SS + s];
            float e1 = g_E1[(size_t)n * SS + s];
            ln1 += c0[k] * e0 + c1[k] * e1;
            tt  += uu[k] * e0;
        }
        float lp0 = l0[(size_t)b * SS + s] - lZ0;
        float lp1 = l1[(size_t)b * SS + s] - lZ1;
        aCe += ln1 * lp0;
        aKl += tt * (logf(fmaxf(tt, 1e-12f)) - lp1);
    }
    aCe = bsum(aCe);
    aKl = bsum(aKl);
    if (t == 0) {
        float lp0t = l0[(size_t)b * SS + targets[b]] - lZ0;
        atomicAdd(&g_acc[1], -(0.9f * lp0t + 0.1f * aCe));
        atomicAdd(&g_acc[2], aKl);
    }
}

__global__ void k_fin(float* __restrict__ out, const float* __restrict__ ramp) {
    if (threadIdx.x == 0) {
        const float invB = 1.0f / 256.0f;
        out[0] = g_acc[0] * invB;
        out[1] = g_acc[1] * invB;
        out[2] = ramp[0] * g_acc[2] * invB;
    }
}

__global__ void k_upd(const float* __restrict__ f, const int* __restrict__ targets,
                      float* __restrict__ out) {
    int b = blockIdx.x, t = threadIdx.x;
    __shared__ int flag;
    int tb = targets[b];
    if (t == 0) {
        int ok = 1;
        for (int j = b + 1; j < BB; j++)
            if (targets[j] == tb) { ok = 0; break; }
        flag = ok;
    }
    __syncthreads();
    if (!flag) return;
    const float* fr = f   + (size_t)tb * FF;
    const float* xr = g_x + (size_t)b  * FF;
    float u[8];
    float s = 0.f;
    #pragma unroll
    for (int i = 0; i < 8; i++) {
        float v = 0.2f * fr[t + i * 256] + 0.8f * xr[t + i * 256];
        u[i] = v; s += v * v;
    }
    s = bsum(s);
    float inv = 1.f / fmaxf(sqrtf(s), 1e-12f);
    float* orow = out + (size_t)tb * FF;
    #pragma unroll
    for (int i = 0; i < 8; i++) orow[t + i * 256] = u[i] * inv;
}

extern "C" void kernel_launch(void* const* d_in, const int* in_sizes, int n_in,
                              void* d_out, int out_size) {
    const float* inputs0   = (const float*)d_in[0];
    const float* l0        = (const float*)d_in[1];
    const float* l1        = (const float*)d_in[2];
    const int*   targets   = (const int*)d_in[3];
    const int*   neighbors = (const int*)d_in[5];
    const float* ndist     = (const float*)d_in[6];
    const float* ramp      = (const float*)d_in[7];
    const float* feat      = (const float*)d_in[8];
    float* out = (float*)d_out;

    static int inited = 0;
    if (!inited) {
        cudaFuncSetAttribute(k_gemm_mma, cudaFuncAttributeMaxDynamicSharedMemorySize,
                             4 * STAGE_B);
        inited = 1;
    }

    k_zero<<<1, 256>>>();
    k_norm<<<BB, 256>>>(inputs0);
    k_convB<<<SS, 256>>>(feat);
    dim3 gg(SS / 64, BB / 128);
    k_gemm_mma<<<gg, 256, 4 * STAGE_B>>>();
    k_nce2<<<BB, 256>>>(targets, feat);
    dim3 gs(BB, 2);
    k_stats<<<gs, 256>>>(l0, l1);
    k_neigh<<<BB, 256>>>(l0, l1, targets, neighbors, ndist);
    k_fin<<<1, 32>>>(out, ramp);
    cudaMemcpyAsync(out + 3, feat, (size_t)SS * FF * sizeof(float),
                    cudaMemcpyDeviceToDevice);
    k_upd<<<BB, 256>>>(feat, targets, out + 3);
}

// round 11
// speedup vs baseline: 3.1686x; 1.4564x over previous
#include <cuda_runtime.h>
#include <cuda_bf16.h>
#include <cuda_fp16.h>
#include <math.h>
#include <stdint.h>

#define BB 256
#define SS 8192
#define FF 2048
#define KNB 20

// ---------------- scratch ----------------
static __device__ float g_x [BB * FF];    // normalized inputs0
static __device__ float g_Z [2 * BB];     // row sumexp (softmax0, softmax1)
static __device__ float g_lZ[2 * BB];     // m + log Z
static __device__ float g_Zn[BB];         // NCE row sum of exp(score - 20)
static __device__ float g_acc[4];         // nce, SCE(=Σ ln1·lp0), Σ lp0t, Σ kl

// bf16 images for the big GEMM
static __device__ __align__(16) __nv_bfloat16 g_Ah[BB * FF];
static __device__ __align__(16) __nv_bfloat16 g_Bh[SS * FF];

// fp16 softmax-numerator images for the neighbor GEMM
static __device__ __align__(16) __half g_Eh [2 * BB * SS];  // [512][8192] rows: n (E0), 256+n (E1)
static __device__ __align__(16) __half g_EhT[SS * 2 * BB];  // [8192][512]
static __device__ __align__(16) __half g_Wh [2 * BB * 2 * BB]; // [512][512], scaled x1024

// ---------------- helpers ----------------
__device__ __forceinline__ uint32_t smem_u32(const void* p) {
    uint32_t a;
    asm("{ .reg .u64 t; cvta.to.shared.u64 t, %1; cvt.u32.u64 %0, t; }" : "=r"(a) : "l"(p));
    return a;
}
__device__ __forceinline__ void cp16(uint32_t d, const void* s) {
    asm volatile("cp.async.cg.shared.global [%0], [%1], 16;" :: "r"(d), "l"(s));
}
__device__ __forceinline__ void cp_commit() {
    asm volatile("cp.async.commit_group;" ::: "memory");
}
__device__ __forceinline__ void cp_wait2() {
    asm volatile("cp.async.wait_group 2;" ::: "memory");
}
__device__ __forceinline__ void ldsm4(uint32_t* r, uint32_t a) {
    asm volatile("ldmatrix.sync.aligned.m8n8.x4.shared.b16 {%0,%1,%2,%3}, [%4];"
                 : "=r"(r[0]), "=r"(r[1]), "=r"(r[2]), "=r"(r[3]) : "r"(a));
}
__device__ __forceinline__ void mma_bf16(float* c, const uint32_t* a, uint32_t b0, uint32_t b1) {
    asm volatile("mma.sync.aligned.m16n8k16.row.col.f32.bf16.bf16.f32 "
                 "{%0,%1,%2,%3},{%4,%5,%6,%7},{%8,%9},{%0,%1,%2,%3};"
                 : "+f"(c[0]), "+f"(c[1]), "+f"(c[2]), "+f"(c[3])
                 : "r"(a[0]), "r"(a[1]), "r"(a[2]), "r"(a[3]), "r"(b0), "r"(b1));
}
__device__ __forceinline__ void mma_f16(float* c, const uint32_t* a, uint32_t b0, uint32_t b1) {
    asm volatile("mma.sync.aligned.m16n8k16.row.col.f32.f16.f16.f32 "
                 "{%0,%1,%2,%3},{%4,%5,%6,%7},{%8,%9},{%0,%1,%2,%3};"
                 : "+f"(c[0]), "+f"(c[1]), "+f"(c[2]), "+f"(c[3])
                 : "r"(a[0]), "r"(a[1]), "r"(a[2]), "r"(a[3]), "r"(b0), "r"(b1));
}

// ---------------- reductions ----------------
__device__ __forceinline__ float bsum(float v) {
    __shared__ float sh[33];
    int lane = threadIdx.x & 31, w = threadIdx.x >> 5, nw = (blockDim.x + 31) >> 5;
    #pragma unroll
    for (int o = 16; o; o >>= 1) v += __shfl_xor_sync(0xffffffffu, v, o);
    if (lane == 0) sh[w] = v;
    __syncthreads();
    v = (threadIdx.x < nw) ? sh[threadIdx.x] : 0.f;
    if (w == 0) {
        #pragma unroll
        for (int o = 16; o; o >>= 1) v += __shfl_xor_sync(0xffffffffu, v, o);
        if (lane == 0) sh[32] = v;
    }
    __syncthreads();
    v = sh[32];
    __syncthreads();
    return v;
}
__device__ __forceinline__ float bmax(float v) {
    __shared__ float sh[33];
    int lane = threadIdx.x & 31, w = threadIdx.x >> 5, nw = (blockDim.x + 31) >> 5;
    #pragma unroll
    for (int o = 16; o; o >>= 1) v = fmaxf(v, __shfl_xor_sync(0xffffffffu, v, o));
    if (lane == 0) sh[w] = v;
    __syncthreads();
    v = (threadIdx.x < nw) ? sh[threadIdx.x] : -1e30f;
    if (w == 0) {
        #pragma unroll
        for (int o = 16; o; o >>= 1) v = fmaxf(v, __shfl_xor_sync(0xffffffffu, v, o));
        if (lane == 0) sh[32] = v;
    }
    __syncthreads();
    v = sh[32];
    __syncthreads();
    return v;
}

// ---------------- kernels ----------------
__global__ void k_zero() {
    if (threadIdx.x < 4) g_acc[threadIdx.x] = 0.f;
    g_Zn[threadIdx.x] = 0.f;   // block of 256
}

// normalize inputs0 -> g_x + bf16 rows. grid=BB, block=256
__global__ void k_norm(const float* __restrict__ in) {
    int b = blockIdx.x, t = threadIdx.x;
    const float4* r = (const float4*)(in + (size_t)b * FF);
    float4 v0 = r[2 * t], v1 = r[2 * t + 1];
    float s = v0.x*v0.x + v0.y*v0.y + v0.z*v0.z + v0.w*v0.w
            + v1.x*v1.x + v1.y*v1.y + v1.z*v1.z + v1.w*v1.w;
    s = bsum(s);
    float inv = 1.f / fmaxf(sqrtf(s), 1e-12f);
    v0.x *= inv; v0.y *= inv; v0.z *= inv; v0.w *= inv;
    v1.x *= inv; v1.y *= inv; v1.z *= inv; v1.w *= inv;
    float4* o = (float4*)(g_x + (size_t)b * FF);
    o[2 * t] = v0; o[2 * t + 1] = v1;
    float v[8] = { v0.x, v0.y, v0.z, v0.w, v1.x, v1.y, v1.z, v1.w };
    __align__(16) unsigned short h[8];
    #pragma unroll
    for (int i = 0; i < 8; i++) h[i] = __bfloat16_as_ushort(__float2bfloat16(v[i]));
    *(uint4*)(g_Ah + (size_t)b * FF + 8 * t) = *(uint4*)h;
}

// features -> bf16 rows AND copy to output (out may be only 4B-aligned). grid=SS, block=256
__global__ void k_convB_copy(const float* __restrict__ f, float* __restrict__ out) {
    int n = blockIdx.x, t = threadIdx.x;
    const float* fr = f + (size_t)n * FF;
    const float4* r = (const float4*)fr;
    float4 v0 = r[2 * t], v1 = r[2 * t + 1];
    float v[8] = { v0.x, v0.y, v0.z, v0.w, v1.x, v1.y, v1.z, v1.w };
    __align__(16) unsigned short h[8];
    #pragma unroll
    for (int i = 0; i < 8; i++) h[i] = __bfloat16_as_ushort(__float2bfloat16(v[i]));
    *(uint4*)(g_Bh + (size_t)n * FF + 8 * t) = *(uint4*)h;
    float* o = out + (size_t)n * FF;
    #pragma unroll
    for (int i = 0; i < 8; i++) o[t + i * 256] = fr[t + i * 256];  // coalesced, L1-hot
}

// ---------------- big GEMM fused with NCE partial sums ----------------
#define STRIDE 40
#define A_TILE_B (128 * STRIDE * 2)
#define B_TILE_B (64 * STRIDE * 2)
#define STAGE_B  (A_TILE_B + B_TILE_B)
#define NCH 64

__device__ __forceinline__ void gemm_issue(int c, int bm, int bn, int tid, uint32_t sb) {
    if (c < NCH) {
        uint32_t st = sb + (c & 3) * STAGE_B;
        #pragma unroll
        for (int i = 0; i < 2; i++) {
            int q = tid + i * 256;
            int row = q >> 2, qc = q & 3;
            cp16(st + row * (STRIDE * 2) + qc * 16,
                 (const char*)(g_Ah + (size_t)(bm + row) * FF + c * 32) + qc * 16);
        }
        {
            int row = tid >> 2, qc = tid & 3;
            cp16(st + A_TILE_B + row * (STRIDE * 2) + qc * 16,
                 (const char*)(g_Bh + (size_t)(bn + row) * FF + c * 32) + qc * 16);
        }
    }
    cp_commit();
}

__global__ void __launch_bounds__(256) k_gemm_mma() {
    extern __shared__ __align__(128) unsigned char smem[];
    uint32_t sb = smem_u32(smem);
    int tid = threadIdx.x;
    int bn = blockIdx.x * 64, bm = blockIdx.y * 128;
    int wid = tid >> 5, lane = tid & 31;
    int wm = (wid >> 1) * 32, wn = (wid & 1) * 32;
    int mi = lane >> 3, lr = lane & 7;
    uint32_t aoff = (uint32_t)(((wm + lr + (mi & 1) * 8) * STRIDE + (mi >> 1) * 8) * 2);
    uint32_t boff = (uint32_t)(A_TILE_B + ((wn + lr + (mi >> 1) * 8) * STRIDE + (mi & 1) * 8) * 2);

    float acc[2][4][4];
    #pragma unroll
    for (int i = 0; i < 2; i++)
        #pragma unroll
        for (int j = 0; j < 4; j++)
            #pragma unroll
            for (int q = 0; q < 4; q++) acc[i][j][q] = 0.f;

    gemm_issue(0, bm, bn, tid, sb);
    gemm_issue(1, bm, bn, tid, sb);
    gemm_issue(2, bm, bn, tid, sb);

    for (int c = 0; c < NCH; c++) {
        cp_wait2();
        __syncthreads();
        gemm_issue(c + 3, bm, bn, tid, sb);
        uint32_t st = sb + (c & 3) * STAGE_B;
        uint32_t a[2][2][4], b[2][2][4];
        #pragma unroll
        for (int ks = 0; ks < 2; ks++) {
            ldsm4(a[ks][0], st + aoff + (0 * 16 * STRIDE + ks * 16) * 2);
            ldsm4(a[ks][1], st + aoff + (1 * 16 * STRIDE + ks * 16) * 2);
            ldsm4(b[ks][0], st + boff + (0 * 16 * STRIDE + ks * 16) * 2);
            ldsm4(b[ks][1], st + boff + (1 * 16 * STRIDE + ks * 16) * 2);
        }
        #pragma unroll
        for (int ks = 0; ks < 2; ks++)
            #pragma unroll
            for (int i = 0; i < 2; i++)
                #pragma unroll
                for (int j = 0; j < 4; j++)
                    mma_bf16(acc[i][j], a[ks][i],
                             b[ks][j >> 1][(j & 1) * 2], b[ks][j >> 1][(j & 1) * 2 + 1]);
    }

    // fused NCE epilogue: per-row sum of exp(20*acc - 20)
    #pragma unroll
    for (int i = 0; i < 2; i++) {
        float z0 = 0.f, z1 = 0.f;
        #pragma unroll
        for (int j = 0; j < 4; j++) {
            z0 += __expf(fmaf(acc[i][j][0], 20.f, -20.f)) + __expf(fmaf(acc[i][j][1], 20.f, -20.f));
            z1 += __expf(fmaf(acc[i][j][2], 20.f, -20.f)) + __expf(fmaf(acc[i][j][3], 20.f, -20.f));
        }
        z0 += __shfl_xor_sync(0xffffffffu, z0, 1);
        z0 += __shfl_xor_sync(0xffffffffu, z0, 2);
        z1 += __shfl_xor_sync(0xffffffffu, z1, 1);
        z1 += __shfl_xor_sync(0xffffffffu, z1, 2);
        if ((lane & 3) == 0) {
            int r0 = bm + wm + i * 16 + (lane >> 2);
            atomicAdd(&g_Zn[r0], z0);
            atomicAdd(&g_Zn[r0 + 8], z1);
        }
    }
}

// NCE finalize + CE target term. grid=BB, block=256
__global__ void k_nce2(const int* __restrict__ targets, const float* __restrict__ feat,
                       const float* __restrict__ l0) {
    int b = blockIdx.x, t = threadIdx.x;
    int tb = targets[b];
    const float4* xr = (const float4*)(g_x + (size_t)b * FF);
    const float4* fr = (const float4*)(feat + (size_t)tb * FF);
    float s = 0.f;
    #pragma unroll
    for (int i = 0; i < 2; i++) {
        float4 xv = xr[t + i * 256], fv = fr[t + i * 256];
        s += xv.x * fv.x + xv.y * fv.y + xv.z * fv.z + xv.w * fv.w;
    }
    s = bsum(s);
    if (t == 0) {
        atomicAdd(&g_acc[0], (20.f + logf(g_Zn[b])) - 20.f * s);
        atomicAdd(&g_acc[2], l0[(size_t)b * SS + tb] - g_lZ[b]);  // lp0[target]
    }
}

// per-row max/sumexp + fp16 E = exp(l - m). grid=(BB,2), block=256
__global__ void k_stats(const float* __restrict__ l0, const float* __restrict__ l1) {
    int b = blockIdx.x, which = blockIdx.y, t = threadIdx.x;
    const float* row = (which ? l1 : l0) + (size_t)b * SS;
    float m = -1e30f;
    for (int s = t; s < SS; s += 256) m = fmaxf(m, row[s]);
    m = bmax(m);
    float z = 0.f;
    __half* er = g_Eh + (size_t)(which * BB + b) * SS;
    for (int s = t; s < SS; s += 256) {
        float e = expf(row[s] - m);
        er[s] = __float2half(e);
        z += e;
    }
    z = bsum(z);
    if (t == 0) {
        g_Z [which * BB + b] = z;
        g_lZ[which * BB + b] = m + logf(z);
    }
}

// build fp16 weight matrix W [512][512] (x1024). grid=BB, block=256
__global__ void k_wbuild(const int* __restrict__ neighbors, const float* __restrict__ ndist) {
    int b = blockIdx.x, t = threadIdx.x;
    __shared__ float rw[512], ru[256], ew[KNB];
    __shared__ int nk[KNB];
    __shared__ float ssum;
    rw[t] = 0.f; rw[t + 256] = 0.f; ru[t] = 0.f;
    if (t < KNB) {
        nk[t] = neighbors[b * KNB + t];
        ew[t] = expf(ndist[b * KNB + t] * (1.0f / 0.6f));
    }
    __syncthreads();
    if (t == 0) { float s = 0.f; for (int k = 0; k < KNB; k++) s += ew[k]; ssum = s; }
    __syncthreads();
    if (t < KNB) {
        float w = ew[t] / (2.0f * ssum);
        int n = nk[t];
        atomicAdd(&rw[n],       w / g_Z[n]);
        atomicAdd(&rw[256 + n], w / g_Z[BB + n]);
        atomicAdd(&ru[n], 1.0f / ((float)KNB * g_Z[n]));
    }
    __syncthreads();
    __half* W0 = g_Wh + (size_t)b * 512;
    __half* W1 = g_Wh + (size_t)(256 + b) * 512;
    W0[t]       = __float2half(rw[t] * 1024.f);
    W0[t + 256] = __float2half(rw[t + 256] * 1024.f);
    W1[t]       = __float2half(ru[t] * 1024.f);
    W1[t + 256] = __float2half(0.f);
}

// transpose g_Eh [512][8192] -> g_EhT [8192][512]. grid=(256,16), block=(32,8)
__global__ void k_trans() {
    __shared__ unsigned short tl[32][33];
    int bx = blockIdx.x, by = blockIdx.y;
    int tx = threadIdx.x, ty = threadIdx.y;
    const unsigned short* in = (const unsigned short*)g_Eh;
    unsigned short* op = (unsigned short*)g_EhT;
    #pragma unroll
    for (int i = 0; i < 4; i++) {
        int n = by * 32 + ty + i * 8;
        tl[ty + i * 8][tx] = in[(size_t)n * SS + bx * 32 + tx];
    }
    __syncthreads();
    #pragma unroll
    for (int i = 0; i < 4; i++) {
        int s = bx * 32 + ty + i * 8;
        op[(size_t)s * 512 + by * 32 + tx] = tl[tx][ty + i * 8];
    }
}

// ---------------- neighbor GEMM, fused CE/KL epilogue ----------------
// O[512,8192] = (W/1024) @ EhT^T ; rows<256: Sigma ln1*lp0 ; rows>=256: Sigma tt*(log tt - lp1)
#define NNCH 16
__device__ __forceinline__ void ngemm_issue(int c, int bm, int bn, int tid, uint32_t sb) {
    if (c < NNCH) {
        uint32_t st = sb + (c & 3) * STAGE_B;
        #pragma unroll
        for (int i = 0; i < 2; i++) {
            int q = tid + i * 256;
            int row = q >> 2, qc = q & 3;
            cp16(st + row * (STRIDE * 2) + qc * 16,
                 (const char*)(g_Wh + (size_t)(bm + row) * 512 + c * 32) + qc * 16);
        }
        {
            int row = tid >> 2, qc = tid & 3;
            cp16(st + A_TILE_B + row * (STRIDE * 2) + qc * 16,
                 (const char*)(g_EhT + (size_t)(bn + row) * 512 + c * 32) + qc * 16);
        }
    }
    cp_commit();
}

__global__ void __launch_bounds__(256) k_ngemm(const float* __restrict__ l0,
                                               const float* __restrict__ l1) {
    extern __shared__ __align__(128) unsigned char smem[];
    uint32_t sb = smem_u32(smem);
    int tid = threadIdx.x;
    int bn = blockIdx.x * 64, bm = blockIdx.y * 128;
    int wid = tid >> 5, lane = tid & 31;
    int wm = (wid >> 1) * 32, wn = (wid & 1) * 32;
    int mi = lane >> 3, lr = lane & 7;
    uint32_t aoff = (uint32_t)(((wm + lr + (mi & 1) * 8) * STRIDE + (mi >> 1) * 8) * 2);
    uint32_t boff = (uint32_t)(A_TILE_B + ((wn + lr + (mi >> 1) * 8) * STRIDE + (mi & 1) * 8) * 2);

    float acc[2][4][4];
    #pragma unroll
    for (int i = 0; i < 2; i++)
        #pragma unroll
        for (int j = 0; j < 4; j++)
            #pragma unroll
            for (int q = 0; q < 4; q++) acc[i][j][q] = 0.f;

    ngemm_issue(0, bm, bn, tid, sb);
    ngemm_issue(1, bm, bn, tid, sb);
    ngemm_issue(2, bm, bn, tid, sb);

    for (int c = 0; c < NNCH; c++) {
        cp_wait2();
        __syncthreads();
        ngemm_issue(c + 3, bm, bn, tid, sb);
        uint32_t st = sb + (c & 3) * STAGE_B;
        uint32_t a[2][2][4], b[2][2][4];
        #pragma unroll
        for (int ks = 0; ks < 2; ks++) {
            ldsm4(a[ks][0], st + aoff + (0 * 16 * STRIDE + ks * 16) * 2);
            ldsm4(a[ks][1], st + aoff + (1 * 16 * STRIDE + ks * 16) * 2);
            ldsm4(b[ks][0], st + boff + (0 * 16 * STRIDE + ks * 16) * 2);
            ldsm4(b[ks][1], st + boff + (1 * 16 * STRIDE + ks * 16) * 2);
        }
        #pragma unroll
        for (int ks = 0; ks < 2; ks++)
            #pragma unroll
            for (int i = 0; i < 2; i++)
                #pragma unroll
                for (int j = 0; j < 4; j++)
                    mma_f16(acc[i][j], a[ks][i],
                            b[ks][j >> 1][(j & 1) * 2], b[ks][j >> 1][(j & 1) * 2 + 1]);
    }

    // fused epilogue
    const float S = 1.0f / 1024.f;
    int isKL = (bm >= 256);
    const float* L = isKL ? l1 : l0;
    int roff = isKL ? 256 : 0;
    float part = 0.f;
    #pragma unroll
    for (int i = 0; i < 2; i++) {
        int r0 = bm + wm + i * 16 + (lane >> 2);
        float lz0 = g_lZ[r0], lz1 = g_lZ[r0 + 8];
        const float* row0 = L + (size_t)(r0 - roff) * SS;
        const float* row1 = row0 + 8 * (size_t)SS;
        #pragma unroll
        for (int j = 0; j < 4; j++) {
            int col = bn + wn + j * 8 + (lane & 3) * 2;
            float2 p0 = *(const float2*)(row0 + col);
            float2 p1 = *(const float2*)(row1 + col);
            float v0 = acc[i][j][0] * S, v1 = acc[i][j][1] * S;
            float v2 = acc[i][j][2] * S, v3 = acc[i][j][3] * S;
            if (isKL) {
                part += v0 * (__logf(fmaxf(v0, 1e-12f)) - (p0.x - lz0));
                part += v1 * (__logf(fmaxf(v1, 1e-12f)) - (p0.y - lz0));
                part += v2 * (__logf(fmaxf(v2, 1e-12f)) - (p1.x - lz1));
                part += v3 * (__logf(fmaxf(v3, 1e-12f)) - (p1.y - lz1));
            } else {
                part += v0 * (p0.x - lz0) + v1 * (p0.y - lz0);
                part += v2 * (p1.x - lz1) + v3 * (p1.y - lz1);
            }
        }
    }
    part = bsum(part);
    if (tid == 0) atomicAdd(&g_acc[isKL ? 3 : 1], part);
}

__global__ void k_fin(float* __restrict__ out, const float* __restrict__ ramp) {
    if (threadIdx.x == 0) {
        const float invB = 1.0f / 256.0f;
        out[0] = g_acc[0] * invB;                                   // loss_nce
        out[1] = -(0.9f * g_acc[2] + 0.1f * g_acc[1]) * invB;       // loss_ce
        out[2] = ramp[0] * g_acc[3] * invB;                         // kl
    }
}

// momentum update of targeted rows (last occurrence wins). grid=BB, block=256
__global__ void k_upd(const float* __restrict__ f, const int* __restrict__ targets,
                      float* __restrict__ out) {
    int b = blockIdx.x, t = threadIdx.x;
    __shared__ int flag;
    int tb = targets[b];
    if (t == 0) {
        int ok = 1;
        for (int j = b + 1; j < BB; j++)
            if (targets[j] == tb) { ok = 0; break; }
        flag = ok;
    }
    __syncthreads();
    if (!flag) return;
    const float* fr = f   + (size_t)tb * FF;
    const float* xr = g_x + (size_t)b  * FF;
    float u[8];
    float s = 0.f;
    #pragma unroll
    for (int i = 0; i < 8; i++) {
        float v = 0.2f * fr[t + i * 256] + 0.8f * xr[t + i * 256];
        u[i] = v; s += v * v;
    }
    s = bsum(s);
    float inv = 1.f / fmaxf(sqrtf(s), 1e-12f);
    float* orow = out + (size_t)tb * FF;
    #pragma unroll
    for (int i = 0; i < 8; i++) orow[t + i * 256] = u[i] * inv;
}

extern "C" void kernel_launch(void* const* d_in, const int* in_sizes, int n_in,
                              void* d_out, int out_size) {
    const float* inputs0   = (const float*)d_in[0];
    const float* l0        = (const float*)d_in[1];
    const float* l1        = (const float*)d_in[2];
    const int*   targets   = (const int*)d_in[3];
    const int*   neighbors = (const int*)d_in[5];
    const float* ndist     = (const float*)d_in[6];
    const float* ramp      = (const float*)d_in[7];
    const float* feat      = (const float*)d_in[8];
    float* out = (float*)d_out;

    static int inited = 0;
    if (!inited) {
        cudaFuncSetAttribute(k_gemm_mma, cudaFuncAttributeMaxDynamicSharedMemorySize,
                             4 * STAGE_B);
        cudaFuncSetAttribute(k_ngemm, cudaFuncAttributeMaxDynamicSharedMemorySize,
                             4 * STAGE_B);
        inited = 1;
    }

    k_zero<<<1, 256>>>();
    k_norm<<<BB, 256>>>(inputs0);
    k_convB_copy<<<SS, 256>>>(feat, out + 3);
    dim3 gg(SS / 64, BB / 128);
    k_gemm_mma<<<gg, 256, 4 * STAGE_B>>>();
    dim3 gs(BB, 2);
    k_stats<<<gs, 256>>>(l0, l1);
    k_nce2<<<BB, 256>>>(targets, feat, l0);
    k_wbuild<<<BB, 256>>>(neighbors, ndist);
    dim3 gt(SS / 32, 16);
    k_trans<<<gt, dim3(32, 8)>>>();
    dim3 gn(SS / 64, 4);
    k_ngemm<<<gn, 256, 4 * STAGE_B>>>(l0, l1);
    k_upd<<<BB, 256>>>(feat, targets, out + 3);
    k_fin<<<1, 32>>>(out, ramp);
}

// round 13
// speedup vs baseline: 3.6252x; 1.1441x over previous
#include <cuda_runtime.h>
#include <cuda_bf16.h>
#include <cuda_fp16.h>
#include <math.h>
#include <stdint.h>

#define BB 256
#define SS 8192
#define FF 2048
#define KNB 20

// ---------------- scratch ----------------
static __device__ float g_x [BB * FF];    // normalized inputs0
static __device__ float g_Z [2 * BB];     // row sumexp (softmax0, softmax1)
static __device__ float g_lZ[2 * BB];     // m + log Z
static __device__ float g_Zn[BB];         // NCE row sum of exp(score - 20)
static __device__ float g_acc[4];         // nce, SCE(=Σ ln1·lp0), Σ lp0t, Σ kl

// bf16 images for the big GEMM
static __device__ __align__(16) __nv_bfloat16 g_Ah[BB * FF];
static __device__ __align__(16) __nv_bfloat16 g_Bh[SS * FF];

// fp16 softmax-numerator images for the neighbor GEMM
static __device__ __align__(16) __half g_Eh [2 * BB * SS];  // [512][8192]
static __device__ __align__(16) __half g_EhT[SS * 2 * BB];  // [8192][512]
static __device__ __align__(16) __half g_Wh [2 * BB * 2 * BB]; // [512][512], x1024

// ---------------- helpers ----------------
__device__ __forceinline__ uint32_t smem_u32(const void* p) {
    uint32_t a;
    asm("{ .reg .u64 t; cvta.to.shared.u64 t, %1; cvt.u32.u64 %0, t; }" : "=r"(a) : "l"(p));
    return a;
}
__device__ __forceinline__ void cp16(uint32_t d, const void* s) {
    asm volatile("cp.async.cg.shared.global [%0], [%1], 16;" :: "r"(d), "l"(s));
}
__device__ __forceinline__ void cp_commit() {
    asm volatile("cp.async.commit_group;" ::: "memory");
}
__device__ __forceinline__ void cp_wait2() {
    asm volatile("cp.async.wait_group 2;" ::: "memory");
}
__device__ __forceinline__ void ldsm4(uint32_t* r, uint32_t a) {
    asm volatile("ldmatrix.sync.aligned.m8n8.x4.shared.b16 {%0,%1,%2,%3}, [%4];"
                 : "=r"(r[0]), "=r"(r[1]), "=r"(r[2]), "=r"(r[3]) : "r"(a));
}
__device__ __forceinline__ void mma_bf16(float* c, const uint32_t* a, uint32_t b0, uint32_t b1) {
    asm volatile("mma.sync.aligned.m16n8k16.row.col.f32.bf16.bf16.f32 "
                 "{%0,%1,%2,%3},{%4,%5,%6,%7},{%8,%9},{%0,%1,%2,%3};"
                 : "+f"(c[0]), "+f"(c[1]), "+f"(c[2]), "+f"(c[3])
                 : "r"(a[0]), "r"(a[1]), "r"(a[2]), "r"(a[3]), "r"(b0), "r"(b1));
}
__device__ __forceinline__ void mma_f16(float* c, const uint32_t* a, uint32_t b0, uint32_t b1) {
    asm volatile("mma.sync.aligned.m16n8k16.row.col.f32.f16.f16.f32 "
                 "{%0,%1,%2,%3},{%4,%5,%6,%7},{%8,%9},{%0,%1,%2,%3};"
                 : "+f"(c[0]), "+f"(c[1]), "+f"(c[2]), "+f"(c[3])
                 : "r"(a[0]), "r"(a[1]), "r"(a[2]), "r"(a[3]), "r"(b0), "r"(b1));
}

// ---------------- reductions ----------------
__device__ __forceinline__ float bsum(float v) {
    __shared__ float sh[33];
    int lane = threadIdx.x & 31, w = threadIdx.x >> 5, nw = (blockDim.x + 31) >> 5;
    #pragma unroll
    for (int o = 16; o; o >>= 1) v += __shfl_xor_sync(0xffffffffu, v, o);
    if (lane == 0) sh[w] = v;
    __syncthreads();
    v = (threadIdx.x < nw) ? sh[threadIdx.x] : 0.f;
    if (w == 0) {
        #pragma unroll
        for (int o = 16; o; o >>= 1) v += __shfl_xor_sync(0xffffffffu, v, o);
        if (lane == 0) sh[32] = v;
    }
    __syncthreads();
    v = sh[32];
    __syncthreads();
    return v;
}
__device__ __forceinline__ float bmax(float v) {
    __shared__ float sh[33];
    int lane = threadIdx.x & 31, w = threadIdx.x >> 5, nw = (blockDim.x + 31) >> 5;
    #pragma unroll
    for (int o = 16; o; o >>= 1) v = fmaxf(v, __shfl_xor_sync(0xffffffffu, v, o));
    if (lane == 0) sh[w] = v;
    __syncthreads();
    v = (threadIdx.x < nw) ? sh[threadIdx.x] : -1e30f;
    if (w == 0) {
        #pragma unroll
        for (int o = 16; o; o >>= 1) v = fmaxf(v, __shfl_xor_sync(0xffffffffu, v, o));
        if (lane == 0) sh[32] = v;
    }
    __syncthreads();
    v = sh[32];
    __syncthreads();
    return v;
}

// ---------------- kernels ----------------
// normalize inputs0 -> g_x + bf16 rows; block 0 also zeroes accumulators. grid=BB
__global__ void k_norm(const float* __restrict__ in) {
    int b = blockIdx.x, t = threadIdx.x;
    if (b == 0) {
        g_Zn[t] = 0.f;
        if (t < 4) g_acc[t] = 0.f;
    }
    const float4* r = (const float4*)(in + (size_t)b * FF);
    float4 v0 = r[2 * t], v1 = r[2 * t + 1];
    float s = v0.x*v0.x + v0.y*v0.y + v0.z*v0.z + v0.w*v0.w
            + v1.x*v1.x + v1.y*v1.y + v1.z*v1.z + v1.w*v1.w;
    s = bsum(s);
    float inv = 1.f / fmaxf(sqrtf(s), 1e-12f);
    v0.x *= inv; v0.y *= inv; v0.z *= inv; v0.w *= inv;
    v1.x *= inv; v1.y *= inv; v1.z *= inv; v1.w *= inv;
    float4* o = (float4*)(g_x + (size_t)b * FF);
    o[2 * t] = v0; o[2 * t + 1] = v1;
    float v[8] = { v0.x, v0.y, v0.z, v0.w, v1.x, v1.y, v1.z, v1.w };
    __align__(16) unsigned short h[8];
    #pragma unroll
    for (int i = 0; i < 8; i++) h[i] = __bfloat16_as_ushort(__float2bfloat16(v[i]));
    *(uint4*)(g_Ah + (size_t)b * FF + 8 * t) = *(uint4*)h;
}

// features -> bf16 rows. grid=SS, block=256
__global__ void k_convB(const float* __restrict__ f) {
    int n = blockIdx.x, t = threadIdx.x;
    const float4* r = (const float4*)(f + (size_t)n * FF);
    float4 v0 = r[2 * t], v1 = r[2 * t + 1];
    float v[8] = { v0.x, v0.y, v0.z, v0.w, v1.x, v1.y, v1.z, v1.w };
    __align__(16) unsigned short h[8];
    #pragma unroll
    for (int i = 0; i < 8; i++) h[i] = __bfloat16_as_ushort(__float2bfloat16(v[i]));
    *(uint4*)(g_Bh + (size_t)n * FF + 8 * t) = *(uint4*)h;
}

// bulk copy features -> out (out only 4B-aligned). grid=2048, block=256
__global__ void k_copy(const float* __restrict__ f, float* __restrict__ out) {
    size_t n4 = (size_t)SS * FF / 4;
    for (size_t i = (size_t)blockIdx.x * blockDim.x + threadIdx.x; i < n4;
         i += (size_t)gridDim.x * blockDim.x) {
        float4 v = ((const float4*)f)[i];
        float* o = out + i * 4;
        o[0] = v.x; o[1] = v.y; o[2] = v.z; o[3] = v.w;
    }
}

// ---------------- big GEMM fused with NCE partial sums ----------------
#define STRIDE 40
#define A_TILE_B (128 * STRIDE * 2)
#define B_TILE_B (64 * STRIDE * 2)
#define STAGE_B  (A_TILE_B + B_TILE_B)
#define NCH 64

__device__ __forceinline__ void gemm_issue(int c, int bm, int bn, int tid, uint32_t sb) {
    if (c < NCH) {
        uint32_t st = sb + (c & 3) * STAGE_B;
        #pragma unroll
        for (int i = 0; i < 2; i++) {
            int q = tid + i * 256;
            int row = q >> 2, qc = q & 3;
            cp16(st + row * (STRIDE * 2) + qc * 16,
                 (const char*)(g_Ah + (size_t)(bm + row) * FF + c * 32) + qc * 16);
        }
        {
            int row = tid >> 2, qc = tid & 3;
            cp16(st + A_TILE_B + row * (STRIDE * 2) + qc * 16,
                 (const char*)(g_Bh + (size_t)(bn + row) * FF + c * 32) + qc * 16);
        }
    }
    cp_commit();
}

__global__ void __launch_bounds__(256) k_gemm_mma() {
    extern __shared__ __align__(128) unsigned char smem[];
    uint32_t sb = smem_u32(smem);
    int tid = threadIdx.x;
    int bn = blockIdx.x * 64, bm = blockIdx.y * 128;
    int wid = tid >> 5, lane = tid & 31;
    int wm = (wid >> 1) * 32, wn = (wid & 1) * 32;
    int mi = lane >> 3, lr = lane & 7;
    uint32_t aoff = (uint32_t)(((wm + lr + (mi & 1) * 8) * STRIDE + (mi >> 1) * 8) * 2);
    uint32_t boff = (uint32_t)(A_TILE_B + ((wn + lr + (mi >> 1) * 8) * STRIDE + (mi & 1) * 8) * 2);

    float acc[2][4][4];
    #pragma unroll
    for (int i = 0; i < 2; i++)
        #pragma unroll
        for (int j = 0; j < 4; j++)
            #pragma unroll
            for (int q = 0; q < 4; q++) acc[i][j][q] = 0.f;

    gemm_issue(0, bm, bn, tid, sb);
    gemm_issue(1, bm, bn, tid, sb);
    gemm_issue(2, bm, bn, tid, sb);

    for (int c = 0; c < NCH; c++) {
        cp_wait2();
        __syncthreads();
        gemm_issue(c + 3, bm, bn, tid, sb);
        uint32_t st = sb + (c & 3) * STAGE_B;
        uint32_t a[2][2][4], b[2][2][4];
        #pragma unroll
        for (int ks = 0; ks < 2; ks++) {
            ldsm4(a[ks][0], st + aoff + (0 * 16 * STRIDE + ks * 16) * 2);
            ldsm4(a[ks][1], st + aoff + (1 * 16 * STRIDE + ks * 16) * 2);
            ldsm4(b[ks][0], st + boff + (0 * 16 * STRIDE + ks * 16) * 2);
            ldsm4(b[ks][1], st + boff + (1 * 16 * STRIDE + ks * 16) * 2);
        }
        #pragma unroll
        for (int ks = 0; ks < 2; ks++)
            #pragma unroll
            for (int i = 0; i < 2; i++)
                #pragma unroll
                for (int j = 0; j < 4; j++)
                    mma_bf16(acc[i][j], a[ks][i],
                             b[ks][j >> 1][(j & 1) * 2], b[ks][j >> 1][(j & 1) * 2 + 1]);
    }

    // fused NCE epilogue: per-row sum of exp(20*acc - 20)
    #pragma unroll
    for (int i = 0; i < 2; i++) {
        float z0 = 0.f, z1 = 0.f;
        #pragma unroll
        for (int j = 0; j < 4; j++) {
            z0 += __expf(fmaf(acc[i][j][0], 20.f, -20.f)) + __expf(fmaf(acc[i][j][1], 20.f, -20.f));
            z1 += __expf(fmaf(acc[i][j][2], 20.f, -20.f)) + __expf(fmaf(acc[i][j][3], 20.f, -20.f));
        }
        z0 += __shfl_xor_sync(0xffffffffu, z0, 1);
        z0 += __shfl_xor_sync(0xffffffffu, z0, 2);
        z1 += __shfl_xor_sync(0xffffffffu, z1, 1);
        z1 += __shfl_xor_sync(0xffffffffu, z1, 2);
        if ((lane & 3) == 0) {
            int r0 = bm + wm + i * 16 + (lane >> 2);
            atomicAdd(&g_Zn[r0], z0);
            atomicAdd(&g_Zn[r0 + 8], z1);
        }
    }
}

// NCE finalize (no g_lZ dependency -> stays on chain1). grid=BB, block=256
__global__ void k_nce2(const int* __restrict__ targets, const float* __restrict__ feat) {
    int b = blockIdx.x, t = threadIdx.x;
    int tb = targets[b];
    const float4* xr = (const float4*)(g_x + (size_t)b * FF);
    const float4* fr = (const float4*)(feat + (size_t)tb * FF);
    float s = 0.f;
    #pragma unroll
    for (int i = 0; i < 2; i++) {
        float4 xv = xr[t + i * 256], fv = fr[t + i * 256];
        s += xv.x * fv.x + xv.y * fv.y + xv.z * fv.z + xv.w * fv.w;
    }
    s = bsum(s);
    if (t == 0) atomicAdd(&g_acc[0], (20.f + logf(g_Zn[b])) - 20.f * s);
}

// per-row max/sumexp + fp16 E = exp(l - m). grid=(BB,2), block=256
__global__ void k_stats(const float* __restrict__ l0, const float* __restrict__ l1) {
    int b = blockIdx.x, which = blockIdx.y, t = threadIdx.x;
    const float* row = (which ? l1 : l0) + (size_t)b * SS;
    float m = -1e30f;
    for (int s = t; s < SS; s += 256) m = fmaxf(m, row[s]);
    m = bmax(m);
    float z = 0.f;
    __half* er = g_Eh + (size_t)(which * BB + b) * SS;
    for (int s = t; s < SS; s += 256) {
        float e = expf(row[s] - m);
        er[s] = __float2half(e);
        z += e;
    }
    z = bsum(z);
    if (t == 0) {
        g_Z [which * BB + b] = z;
        g_lZ[which * BB + b] = m + logf(z);
    }
}

// build fp16 weight matrix W [512][512] (x1024) + CE target term. grid=BB, block=256
__global__ void k_wbuild(const int* __restrict__ neighbors, const float* __restrict__ ndist,
                         const int* __restrict__ targets, const float* __restrict__ l0) {
    int b = blockIdx.x, t = threadIdx.x;
    __shared__ float rw[512], ru[256], ew[KNB];
    __shared__ int nk[KNB];
    __shared__ float ssum;
    rw[t] = 0.f; rw[t + 256] = 0.f; ru[t] = 0.f;
    if (t < KNB) {
        nk[t] = neighbors[b * KNB + t];
        ew[t] = expf(ndist[b * KNB + t] * (1.0f / 0.6f));
    }
    __syncthreads();
    if (t == 0) { float s = 0.f; for (int k = 0; k < KNB; k++) s += ew[k]; ssum = s; }
    __syncthreads();
    if (t < KNB) {
        float w = ew[t] / (2.0f * ssum);
        int n = nk[t];
        atomicAdd(&rw[n],       w / g_Z[n]);
        atomicAdd(&rw[256 + n], w / g_Z[BB + n]);
        atomicAdd(&ru[n], 1.0f / ((float)KNB * g_Z[n]));
    }
    __syncthreads();
    __half* W0 = g_Wh + (size_t)b * 512;
    __half* W1 = g_Wh + (size_t)(256 + b) * 512;
    W0[t]       = __float2half(rw[t] * 1024.f);
    W0[t + 256] = __float2half(rw[t + 256] * 1024.f);
    W1[t]       = __float2half(ru[t] * 1024.f);
    W1[t + 256] = __float2half(0.f);
    if (t == 0)
        atomicAdd(&g_acc[2], l0[(size_t)b * SS + targets[b]] - g_lZ[b]);  // lp0[target]
}

// transpose g_Eh [512][8192] -> g_EhT [8192][512]. grid=(256,16), block=(32,8)
__global__ void k_trans() {
    __shared__ unsigned short tl[32][33];
    int bx = blockIdx.x, by = blockIdx.y;
    int tx = threadIdx.x, ty = threadIdx.y;
    const unsigned short* in = (const unsigned short*)g_Eh;
    unsigned short* op = (unsigned short*)g_EhT;
    #pragma unroll
    for (int i = 0; i < 4; i++) {
        int n = by * 32 + ty + i * 8;
        tl[ty + i * 8][tx] = in[(size_t)n * SS + bx * 32 + tx];
    }
    __syncthreads();
    #pragma unroll
    for (int i = 0; i < 4; i++) {
        int s = bx * 32 + ty + i * 8;
        op[(size_t)s * 512 + by * 32 + tx] = tl[tx][ty + i * 8];
    }
}

// ---------------- neighbor GEMM, fused CE/KL epilogue ----------------
#define NNCH 16
__device__ __forceinline__ void ngemm_issue(int c, int bm, int bn, int tid, uint32_t sb) {
    if (c < NNCH) {
        uint32_t st = sb + (c & 3) * STAGE_B;
        #pragma unroll
        for (int i = 0; i < 2; i++) {
            int q = tid + i * 256;
            int row = q >> 2, qc = q & 3;
            cp16(st + row * (STRIDE * 2) + qc * 16,
                 (const char*)(g_Wh + (size_t)(bm + row) * 512 + c * 32) + qc * 16);
        }
        {
            int row = tid >> 2, qc = tid & 3;
            cp16(st + A_TILE_B + row * (STRIDE * 2) + qc * 16,
                 (const char*)(g_EhT + (size_t)(bn + row) * 512 + c * 32) + qc * 16);
        }
    }
    cp_commit();
}

__global__ void __launch_bounds__(256) k_ngemm(const float* __restrict__ l0,
                                               const float* __restrict__ l1) {
    extern __shared__ __align__(128) unsigned char smem[];
    uint32_t sb = smem_u32(smem);
    int tid = threadIdx.x;
    int bn = blockIdx.x * 64, bm = blockIdx.y * 128;
    int wid = tid >> 5, lane = tid & 31;
    int wm = (wid >> 1) * 32, wn = (wid & 1) * 32;
    int mi = lane >> 3, lr = lane & 7;
    uint32_t aoff = (uint32_t)(((wm + lr + (mi & 1) * 8) * STRIDE + (mi >> 1) * 8) * 2);
    uint32_t boff = (uint32_t)(A_TILE_B + ((wn + lr + (mi >> 1) * 8) * STRIDE + (mi & 1) * 8) * 2);

    float acc[2][4][4];
    #pragma unroll
    for (int i = 0; i < 2; i++)
        #pragma unroll
        for (int j = 0; j < 4; j++)
            #pragma unroll
            for (int q = 0; q < 4; q++) acc[i][j][q] = 0.f;

    ngemm_issue(0, bm, bn, tid, sb);
    ngemm_issue(1, bm, bn, tid, sb);
    ngemm_issue(2, bm, bn, tid, sb);

    for (int c = 0; c < NNCH; c++) {
        cp_wait2();
        __syncthreads();
        ngemm_issue(c + 3, bm, bn, tid, sb);
        uint32_t st = sb + (c & 3) * STAGE_B;
        uint32_t a[2][2][4], b[2][2][4];
        #pragma unroll
        for (int ks = 0; ks < 2; ks++) {
            ldsm4(a[ks][0], st + aoff + (0 * 16 * STRIDE + ks * 16) * 2);
            ldsm4(a[ks][1], st + aoff + (1 * 16 * STRIDE + ks * 16) * 2);
            ldsm4(b[ks][0], st + boff + (0 * 16 * STRIDE + ks * 16) * 2);
            ldsm4(b[ks][1], st + boff + (1 * 16 * STRIDE + ks * 16) * 2);
        }
        #pragma unroll
        for (int ks = 0; ks < 2; ks++)
            #pragma unroll
            for (int i = 0; i < 2; i++)
                #pragma unroll
                for (int j = 0; j < 4; j++)
                    mma_f16(acc[i][j], a[ks][i],
                            b[ks][j >> 1][(j & 1) * 2], b[ks][j >> 1][(j & 1) * 2 + 1]);
    }

    // fused epilogue
    const float S = 1.0f / 1024.f;
    int isKL = (bm >= 256);
    const float* L = isKL ? l1 : l0;
    int roff = isKL ? 256 : 0;
    float part = 0.f;
    #pragma unroll
    for (int i = 0; i < 2; i++) {
        int r0 = bm + wm + i * 16 + (lane >> 2);
        float lz0 = g_lZ[r0], lz1 = g_lZ[r0 + 8];
        const float* row0 = L + (size_t)(r0 - roff) * SS;
        const float* row1 = row0 + 8 * (size_t)SS;
        #pragma unroll
        for (int j = 0; j < 4; j++) {
            int col = bn + wn + j * 8 + (lane & 3) * 2;
            float2 p0 = *(const float2*)(row0 + col);
            float2 p1 = *(const float2*)(row1 + col);
            float v0 = acc[i][j][0] * S, v1 = acc[i][j][1] * S;
            float v2 = acc[i][j][2] * S, v3 = acc[i][j][3] * S;
            if (isKL) {
                part += v0 * (__logf(fmaxf(v0, 1e-12f)) - (p0.x - lz0));
                part += v1 * (__logf(fmaxf(v1, 1e-12f)) - (p0.y - lz0));
                part += v2 * (__logf(fmaxf(v2, 1e-12f)) - (p1.x - lz1));
                part += v3 * (__logf(fmaxf(v3, 1e-12f)) - (p1.y - lz1));
            } else {
                part += v0 * (p0.x - lz0) + v1 * (p0.y - lz0);
                part += v2 * (p1.x - lz1) + v3 * (p1.y - lz1);
            }
        }
    }
    part = bsum(part);
    if (tid == 0) atomicAdd(&g_acc[isKL ? 3 : 1], part);
}

__global__ void k_fin(float* __restrict__ out, const float* __restrict__ ramp) {
    if (threadIdx.x == 0) {
        const float invB = 1.0f / 256.0f;
        out[0] = g_acc[0] * invB;                                   // loss_nce
        out[1] = -(0.9f * g_acc[2] + 0.1f * g_acc[1]) * invB;       // loss_ce
        out[2] = ramp[0] * g_acc[3] * invB;                         // kl
    }
}

// momentum update of targeted rows (last occurrence wins). grid=BB, block=256
__global__ void k_upd(const float* __restrict__ f, const int* __restrict__ targets,
                      float* __restrict__ out) {
    int b = blockIdx.x, t = threadIdx.x;
    __shared__ int flag;
    int tb = targets[b];
    if (t == 0) {
        int ok = 1;
        for (int j = b + 1; j < BB; j++)
            if (targets[j] == tb) { ok = 0; break; }
        flag = ok;
    }
    __syncthreads();
    if (!flag) return;
    const float* fr = f   + (size_t)tb * FF;
    const float* xr = g_x + (size_t)b  * FF;
    float u[8];
    float s = 0.f;
    #pragma unroll
    for (int i = 0; i < 8; i++) {
        float v = 0.2f * fr[t + i * 256] + 0.8f * xr[t + i * 256];
        u[i] = v; s += v * v;
    }
    s = bsum(s);
    float inv = 1.f / fmaxf(sqrtf(s), 1e-12f);
    float* orow = out + (size_t)tb * FF;
    #pragma unroll
    for (int i = 0; i < 8; i++) orow[t + i * 256] = u[i] * inv;
}

extern "C" void kernel_launch(void* const* d_in, const int* in_sizes, int n_in,
                              void* d_out, int out_size) {
    const float* inputs0   = (const float*)d_in[0];
    const float* l0        = (const float*)d_in[1];
    const float* l1        = (const float*)d_in[2];
    const int*   targets   = (const int*)d_in[3];
    const int*   neighbors = (const int*)d_in[5];
    const float* ndist     = (const float*)d_in[6];
    const float* ramp      = (const float*)d_in[7];
    const float* feat      = (const float*)d_in[8];
    float* out = (float*)d_out;

    static cudaStream_t s1 = 0, s2 = 0;
    static cudaEvent_t e_norm = 0, e_c1 = 0, e_c2 = 0;
    static int inited = 0;
    if (!inited) {
        cudaFuncSetAttribute(k_gemm_mma, cudaFuncAttributeMaxDynamicSharedMemorySize,
                             4 * STAGE_B);
        cudaFuncSetAttribute(k_ngemm, cudaFuncAttributeMaxDynamicSharedMemorySize,
                             4 * STAGE_B);
        cudaStreamCreateWithFlags(&s1, cudaStreamNonBlocking);
        cudaStreamCreateWithFlags(&s2, cudaStreamNonBlocking);
        cudaEventCreateWithFlags(&e_norm, cudaEventDisableTiming);
        cudaEventCreateWithFlags(&e_c1, cudaEventDisableTiming);
        cudaEventCreateWithFlags(&e_c2, cudaEventDisableTiming);
        inited = 1;
    }

    // chain1 head (also zeroes accumulators)
    k_norm<<<BB, 256>>>(inputs0);
    cudaEventRecord(e_norm, 0);

    // ---- fork chain3: feature copy + momentum update ----
    cudaStreamWaitEvent(s1, e_norm, 0);
    k_copy<<<2048, 256, 0, s1>>>(feat, out + 3);
    k_upd<<<BB, 256, 0, s1>>>(feat, targets, out + 3);
    cudaEventRecord(e_c1, s1);

    // ---- fork chain2: softmax stats -> W build -> transpose -> neighbor GEMM ----
    cudaStreamWaitEvent(s2, e_norm, 0);
    dim3 gs(BB, 2);
    k_stats<<<gs, 256, 0, s2>>>(l0, l1);
    k_wbuild<<<BB, 256, 0, s2>>>(neighbors, ndist, targets, l0);
    dim3 gt(SS / 32, 16);
    k_trans<<<gt, dim3(32, 8), 0, s2>>>();
    dim3 gn(SS / 64, 4);
    k_ngemm<<<gn, 256, 4 * STAGE_B, s2>>>(l0, l1);
    cudaEventRecord(e_c2, s2);

    // ---- chain1 continues on the main stream ----
    k_convB<<<SS, 256>>>(feat);
    dim3 gg(SS / 64, BB / 128);
    k_gemm_mma<<<gg, 256, 4 * STAGE_B>>>();
    k_nce2<<<BB, 256>>>(targets, feat);

    // join and finalize
    cudaStreamWaitEvent(0, e_c1, 0);
    cudaStreamWaitEvent(0, e_c2, 0);
    k_fin<<<1, 32>>>(out, ramp);
}

// round 14
// speedup vs baseline: 3.6322x; 1.0019x over previous
#include <cuda_runtime.h>
#include <cuda_bf16.h>
#include <cuda_fp16.h>
#include <math.h>
#include <stdint.h>

#define BB 256
#define SS 8192
#define FF 2048
#define KNB 20

// ---------------- scratch ----------------
static __device__ float g_x [BB * FF];    // normalized inputs0
static __device__ float g_Z [2 * BB];     // row sumexp (softmax0, softmax1)
static __device__ float g_lZ[2 * BB];     // m + log Z
static __device__ float g_Zn[BB];         // NCE row sum of exp(score - 20)
static __device__ float g_acc[4];         // nce, SCE(=Σ ln1·lp0), Σ lp0t, Σ kl

// bf16 images for the big GEMM
static __device__ __align__(16) __nv_bfloat16 g_Ah[BB * FF];
static __device__ __align__(16) __nv_bfloat16 g_Bh[SS * FF];

// fp16 softmax-numerator image for the neighbor GEMM (rows = contraction index k)
static __device__ __align__(16) __half g_Eh [2 * BB * SS];  // [512][8192]
static __device__ __align__(16) __half g_Wh [2 * BB * 2 * BB]; // [512][512], x1024

// ---------------- helpers ----------------
__device__ __forceinline__ uint32_t smem_u32(const void* p) {
    uint32_t a;
    asm("{ .reg .u64 t; cvta.to.shared.u64 t, %1; cvt.u32.u64 %0, t; }" : "=r"(a) : "l"(p));
    return a;
}
__device__ __forceinline__ void cp16(uint32_t d, const void* s) {
    asm volatile("cp.async.cg.shared.global [%0], [%1], 16;" :: "r"(d), "l"(s));
}
__device__ __forceinline__ void cp_commit() {
    asm volatile("cp.async.commit_group;" ::: "memory");
}
__device__ __forceinline__ void cp_wait2() {
    asm volatile("cp.async.wait_group 2;" ::: "memory");
}
__device__ __forceinline__ void ldsm4(uint32_t* r, uint32_t a) {
    asm volatile("ldmatrix.sync.aligned.m8n8.x4.shared.b16 {%0,%1,%2,%3}, [%4];"
                 : "=r"(r[0]), "=r"(r[1]), "=r"(r[2]), "=r"(r[3]) : "r"(a));
}
__device__ __forceinline__ void ldsm4t(uint32_t* r, uint32_t a) {
    asm volatile("ldmatrix.sync.aligned.m8n8.x4.trans.shared.b16 {%0,%1,%2,%3}, [%4];"
                 : "=r"(r[0]), "=r"(r[1]), "=r"(r[2]), "=r"(r[3]) : "r"(a));
}
__device__ __forceinline__ void mma_bf16(float* c, const uint32_t* a, uint32_t b0, uint32_t b1) {
    asm volatile("mma.sync.aligned.m16n8k16.row.col.f32.bf16.bf16.f32 "
                 "{%0,%1,%2,%3},{%4,%5,%6,%7},{%8,%9},{%0,%1,%2,%3};"
                 : "+f"(c[0]), "+f"(c[1]), "+f"(c[2]), "+f"(c[3])
                 : "r"(a[0]), "r"(a[1]), "r"(a[2]), "r"(a[3]), "r"(b0), "r"(b1));
}
__device__ __forceinline__ void mma_f16(float* c, const uint32_t* a, uint32_t b0, uint32_t b1) {
    asm volatile("mma.sync.aligned.m16n8k16.row.col.f32.f16.f16.f32 "
                 "{%0,%1,%2,%3},{%4,%5,%6,%7},{%8,%9},{%0,%1,%2,%3};"
                 : "+f"(c[0]), "+f"(c[1]), "+f"(c[2]), "+f"(c[3])
                 : "r"(a[0]), "r"(a[1]), "r"(a[2]), "r"(a[3]), "r"(b0), "r"(b1));
}

// ---------------- reductions ----------------
__device__ __forceinline__ float bsum(float v) {
    __shared__ float sh[33];
    int lane = threadIdx.x & 31, w = threadIdx.x >> 5, nw = (blockDim.x + 31) >> 5;
    #pragma unroll
    for (int o = 16; o; o >>= 1) v += __shfl_xor_sync(0xffffffffu, v, o);
    if (lane == 0) sh[w] = v;
    __syncthreads();
    v = (threadIdx.x < nw) ? sh[threadIdx.x] : 0.f;
    if (w == 0) {
        #pragma unroll
        for (int o = 16; o; o >>= 1) v += __shfl_xor_sync(0xffffffffu, v, o);
        if (lane == 0) sh[32] = v;
    }
    __syncthreads();
    v = sh[32];
    __syncthreads();
    return v;
}
__device__ __forceinline__ float bmax(float v) {
    __shared__ float sh[33];
    int lane = threadIdx.x & 31, w = threadIdx.x >> 5, nw = (blockDim.x + 31) >> 5;
    #pragma unroll
    for (int o = 16; o; o >>= 1) v = fmaxf(v, __shfl_xor_sync(0xffffffffu, v, o));
    if (lane == 0) sh[w] = v;
    __syncthreads();
    v = (threadIdx.x < nw) ? sh[threadIdx.x] : -1e30f;
    if (w == 0) {
        #pragma unroll
        for (int o = 16; o; o >>= 1) v = fmaxf(v, __shfl_xor_sync(0xffffffffu, v, o));
        if (lane == 0) sh[32] = v;
    }
    __syncthreads();
    v = sh[32];
    __syncthreads();
    return v;
}

// ---------------- kernels ----------------
// normalize inputs0 -> g_x + bf16 rows; block 0 also zeroes accumulators. grid=BB
__global__ void k_norm(const float* __restrict__ in) {
    int b = blockIdx.x, t = threadIdx.x;
    if (b == 0) {
        g_Zn[t] = 0.f;
        if (t < 4) g_acc[t] = 0.f;
    }
    const float4* r = (const float4*)(in + (size_t)b * FF);
    float4 v0 = r[2 * t], v1 = r[2 * t + 1];
    float s = v0.x*v0.x + v0.y*v0.y + v0.z*v0.z + v0.w*v0.w
            + v1.x*v1.x + v1.y*v1.y + v1.z*v1.z + v1.w*v1.w;
    s = bsum(s);
    float inv = 1.f / fmaxf(sqrtf(s), 1e-12f);
    v0.x *= inv; v0.y *= inv; v0.z *= inv; v0.w *= inv;
    v1.x *= inv; v1.y *= inv; v1.z *= inv; v1.w *= inv;
    float4* o = (float4*)(g_x + (size_t)b * FF);
    o[2 * t] = v0; o[2 * t + 1] = v1;
    float v[8] = { v0.x, v0.y, v0.z, v0.w, v1.x, v1.y, v1.z, v1.w };
    __align__(16) unsigned short h[8];
    #pragma unroll
    for (int i = 0; i < 8; i++) h[i] = __bfloat16_as_ushort(__float2bfloat16(v[i]));
    *(uint4*)(g_Ah + (size_t)b * FF + 8 * t) = *(uint4*)h;
}

// features -> bf16 rows. grid=SS, block=256
__global__ void k_convB(const float* __restrict__ f) {
    int n = blockIdx.x, t = threadIdx.x;
    const float4* r = (const float4*)(f + (size_t)n * FF);
    float4 v0 = r[2 * t], v1 = r[2 * t + 1];
    float v[8] = { v0.x, v0.y, v0.z, v0.w, v1.x, v1.y, v1.z, v1.w };
    __align__(16) unsigned short h[8];
    #pragma unroll
    for (int i = 0; i < 8; i++) h[i] = __bfloat16_as_ushort(__float2bfloat16(v[i]));
    *(uint4*)(g_Bh + (size_t)n * FF + 8 * t) = *(uint4*)h;
}

// bulk copy features -> out (out only 4B-aligned). grid=2048, block=256
__global__ void k_copy(const float* __restrict__ f, float* __restrict__ out) {
    size_t n4 = (size_t)SS * FF / 4;
    for (size_t i = (size_t)blockIdx.x * blockDim.x + threadIdx.x; i < n4;
         i += (size_t)gridDim.x * blockDim.x) {
        float4 v = ((const float4*)f)[i];
        float* o = out + i * 4;
        o[0] = v.x; o[1] = v.y; o[2] = v.z; o[3] = v.w;
    }
}

// ---------------- big GEMM fused with NCE partial sums ----------------
#define STRIDE 40
#define A_TILE_B (128 * STRIDE * 2)
#define B_TILE_B (64 * STRIDE * 2)
#define STAGE_B  (A_TILE_B + B_TILE_B)
#define NCH 64

__device__ __forceinline__ void gemm_issue(int c, int bm, int bn, int tid, uint32_t sb) {
    if (c < NCH) {
        uint32_t st = sb + (c & 3) * STAGE_B;
        #pragma unroll
        for (int i = 0; i < 2; i++) {
            int q = tid + i * 256;
            int row = q >> 2, qc = q & 3;
            cp16(st + row * (STRIDE * 2) + qc * 16,
                 (const char*)(g_Ah + (size_t)(bm + row) * FF + c * 32) + qc * 16);
        }
        {
            int row = tid >> 2, qc = tid & 3;
            cp16(st + A_TILE_B + row * (STRIDE * 2) + qc * 16,
                 (const char*)(g_Bh + (size_t)(bn + row) * FF + c * 32) + qc * 16);
        }
    }
    cp_commit();
}

__global__ void __launch_bounds__(256) k_gemm_mma() {
    extern __shared__ __align__(128) unsigned char smem[];
    uint32_t sb = smem_u32(smem);
    int tid = threadIdx.x;
    int bn = blockIdx.x * 64, bm = blockIdx.y * 128;
    int wid = tid >> 5, lane = tid & 31;
    int wm = (wid >> 1) * 32, wn = (wid & 1) * 32;
    int mi = lane >> 3, lr = lane & 7;
    uint32_t aoff = (uint32_t)(((wm + lr + (mi & 1) * 8) * STRIDE + (mi >> 1) * 8) * 2);
    uint32_t boff = (uint32_t)(A_TILE_B + ((wn + lr + (mi >> 1) * 8) * STRIDE + (mi & 1) * 8) * 2);

    float acc[2][4][4];
    #pragma unroll
    for (int i = 0; i < 2; i++)
        #pragma unroll
        for (int j = 0; j < 4; j++)
            #pragma unroll
            for (int q = 0; q < 4; q++) acc[i][j][q] = 0.f;

    gemm_issue(0, bm, bn, tid, sb);
    gemm_issue(1, bm, bn, tid, sb);
    gemm_issue(2, bm, bn, tid, sb);

    for (int c = 0; c < NCH; c++) {
        cp_wait2();
        __syncthreads();
        gemm_issue(c + 3, bm, bn, tid, sb);
        uint32_t st = sb + (c & 3) * STAGE_B;
        uint32_t a[2][2][4], b[2][2][4];
        #pragma unroll
        for (int ks = 0; ks < 2; ks++) {
            ldsm4(a[ks][0], st + aoff + (0 * 16 * STRIDE + ks * 16) * 2);
            ldsm4(a[ks][1], st + aoff + (1 * 16 * STRIDE + ks * 16) * 2);
            ldsm4(b[ks][0], st + boff + (0 * 16 * STRIDE + ks * 16) * 2);
            ldsm4(b[ks][1], st + boff + (1 * 16 * STRIDE + ks * 16) * 2);
        }
        #pragma unroll
        for (int ks = 0; ks < 2; ks++)
            #pragma unroll
            for (int i = 0; i < 2; i++)
                #pragma unroll
                for (int j = 0; j < 4; j++)
                    mma_bf16(acc[i][j], a[ks][i],
                             b[ks][j >> 1][(j & 1) * 2], b[ks][j >> 1][(j & 1) * 2 + 1]);
    }

    // fused NCE epilogue: per-row sum of exp(20*acc - 20)
    #pragma unroll
    for (int i = 0; i < 2; i++) {
        float z0 = 0.f, z1 = 0.f;
        #pragma unroll
        for (int j = 0; j < 4; j++) {
            z0 += __expf(fmaf(acc[i][j][0], 20.f, -20.f)) + __expf(fmaf(acc[i][j][1], 20.f, -20.f));
            z1 += __expf(fmaf(acc[i][j][2], 20.f, -20.f)) + __expf(fmaf(acc[i][j][3], 20.f, -20.f));
        }
        z0 += __shfl_xor_sync(0xffffffffu, z0, 1);
        z0 += __shfl_xor_sync(0xffffffffu, z0, 2);
        z1 += __shfl_xor_sync(0xffffffffu, z1, 1);
        z1 += __shfl_xor_sync(0xffffffffu, z1, 2);
        if ((lane & 3) == 0) {
            int r0 = bm + wm + i * 16 + (lane >> 2);
            atomicAdd(&g_Zn[r0], z0);
            atomicAdd(&g_Zn[r0 + 8], z1);
        }
    }
}

// NCE finalize. grid=BB, block=256
__global__ void k_nce2(const int* __restrict__ targets, const float* __restrict__ feat) {
    int b = blockIdx.x, t = threadIdx.x;
    int tb = targets[b];
    const float4* xr = (const float4*)(g_x + (size_t)b * FF);
    const float4* fr = (const float4*)(feat + (size_t)tb * FF);
    float s = 0.f;
    #pragma unroll
    for (int i = 0; i < 2; i++) {
        float4 xv = xr[t + i * 256], fv = fr[t + i * 256];
        s += xv.x * fv.x + xv.y * fv.y + xv.z * fv.z + xv.w * fv.w;
    }
    s = bsum(s);
    if (t == 0) atomicAdd(&g_acc[0], (20.f + logf(g_Zn[b])) - 20.f * s);
}

// per-row max/sumexp + fp16 E = exp(l - m). grid=(BB,2), block=256
__global__ void k_stats(const float* __restrict__ l0, const float* __restrict__ l1) {
    int b = blockIdx.x, which = blockIdx.y, t = threadIdx.x;
    const float* row = (which ? l1 : l0) + (size_t)b * SS;
    float m = -1e30f;
    for (int s = t; s < SS; s += 256) m = fmaxf(m, row[s]);
    m = bmax(m);
    float z = 0.f;
    __half* er = g_Eh + (size_t)(which * BB + b) * SS;
    for (int s = t; s < SS; s += 256) {
        float e = expf(row[s] - m);
        er[s] = __float2half(e);
        z += e;
    }
    z = bsum(z);
    if (t == 0) {
        g_Z [which * BB + b] = z;
        g_lZ[which * BB + b] = m + logf(z);
    }
}

// build fp16 weight matrix W [512][512] (x1024) + CE target term. grid=BB, block=256
__global__ void k_wbuild(const int* __restrict__ neighbors, const float* __restrict__ ndist,
                         const int* __restrict__ targets, const float* __restrict__ l0) {
    int b = blockIdx.x, t = threadIdx.x;
    __shared__ float rw[512], ru[256], ew[KNB];
    __shared__ int nk[KNB];
    __shared__ float ssum;
    rw[t] = 0.f; rw[t + 256] = 0.f; ru[t] = 0.f;
    if (t < KNB) {
        nk[t] = neighbors[b * KNB + t];
        ew[t] = expf(ndist[b * KNB + t] * (1.0f / 0.6f));
    }
    __syncthreads();
    if (t == 0) { float s = 0.f; for (int k = 0; k < KNB; k++) s += ew[k]; ssum = s; }
    __syncthreads();
    if (t < KNB) {
        float w = ew[t] / (2.0f * ssum);
        int n = nk[t];
        atomicAdd(&rw[n],       w / g_Z[n]);
        atomicAdd(&rw[256 + n], w / g_Z[BB + n]);
        atomicAdd(&ru[n], 1.0f / ((float)KNB * g_Z[n]));
    }
    __syncthreads();
    __half* W0 = g_Wh + (size_t)b * 512;
    __half* W1 = g_Wh + (size_t)(256 + b) * 512;
    W0[t]       = __float2half(rw[t] * 1024.f);
    W0[t + 256] = __float2half(rw[t + 256] * 1024.f);
    W1[t]       = __float2half(ru[t] * 1024.f);
    W1[t + 256] = __float2half(0.f);
    if (t == 0)
        atomicAdd(&g_acc[2], l0[(size_t)b * SS + targets[b]] - g_lZ[b]);  // lp0[target]
}

// ---------------- neighbor GEMM, fused CE/KL epilogue ----------------
// O[512,8192] = (W/1024) @ E ; B tiles straight from g_Eh via ldmatrix.trans.
#define NNCH 16
#define ESTR 144                         // E-tile smem row stride (9 x 16B, conflict-free)
#define EOFF A_TILE_B                    // E tile placed after A (W) tile
#define STAGE2_B (A_TILE_B + 32 * ESTR)  // 10240 + 4608 = 14848

__device__ __forceinline__ void ngemm_issue(int c, int bm, int bn, int tid, uint32_t sb) {
    if (c < NNCH) {
        uint32_t st = sb + (c & 3) * STAGE2_B;
        #pragma unroll
        for (int i = 0; i < 2; i++) {          // W tile: 128 rows x 64B (stride 80B)
            int q = tid + i * 256;
            int row = q >> 2, qc = q & 3;
            cp16(st + row * (STRIDE * 2) + qc * 16,
                 (const char*)(g_Wh + (size_t)(bm + row) * 512 + c * 32) + qc * 16);
        }
        {                                       // E tile: 32 k-rows x 128B (stride 144B)
            int row = tid >> 3, seg = tid & 7;
            cp16(st + EOFF + row * ESTR + seg * 16,
                 (const char*)(g_Eh + (size_t)(c * 32 + row) * SS + bn + seg * 8));
        }
    }
    cp_commit();
}

__global__ void __launch_bounds__(256) k_ngemm(const float* __restrict__ l0,
                                               const float* __restrict__ l1) {
    extern __shared__ __align__(128) unsigned char smem[];
    uint32_t sb = smem_u32(smem);
    int tid = threadIdx.x;
    int bn = blockIdx.x * 64, bm = blockIdx.y * 128;
    int wid = tid >> 5, lane = tid & 31;
    int wm = (wid >> 1) * 32, wn = (wid & 1) * 32;
    int mi = lane >> 3, lr = lane & 7;
    uint32_t aoff = (uint32_t)(((wm + lr + (mi & 1) * 8) * STRIDE + (mi >> 1) * 8) * 2);
    // trans-ldmatrix base for E tile: group g=mi -> (k += (g&1)*8, n += (g>>1)*8)
    uint32_t ebase = (uint32_t)(EOFF + ((mi & 1) * 8 + lr) * ESTR + (wn + (mi >> 1) * 8) * 2);

    float acc[2][4][4];
    #pragma unroll
    for (int i = 0; i < 2; i++)
        #pragma unroll
        for (int j = 0; j < 4; j++)
            #pragma unroll
            for (int q = 0; q < 4; q++) acc[i][j][q] = 0.f;

    ngemm_issue(0, bm, bn, tid, sb);
    ngemm_issue(1, bm, bn, tid, sb);
    ngemm_issue(2, bm, bn, tid, sb);

    for (int c = 0; c < NNCH; c++) {
        cp_wait2();
        __syncthreads();
        ngemm_issue(c + 3, bm, bn, tid, sb);
        uint32_t st = sb + (c & 3) * STAGE2_B;
        uint32_t a[2][2][4], b[2][2][4];
        #pragma unroll
        for (int ks = 0; ks < 2; ks++) {
            ldsm4 (a[ks][0], st + aoff + (0 * 16 * STRIDE + ks * 16) * 2);
            ldsm4 (a[ks][1], st + aoff + (1 * 16 * STRIDE + ks * 16) * 2);
            // b[ks][jp]: x4.trans covering k16 x n16 at (k = ks*16, n = wn + jp*16)
            ldsm4t(b[ks][0], st + ebase + ks * (16 * ESTR) + 0 * 32);
            ldsm4t(b[ks][1], st + ebase + ks * (16 * ESTR) + 1 * 32);
        }
        #pragma unroll
        for (int ks = 0; ks < 2; ks++)
            #pragma unroll
            for (int i = 0; i < 2; i++)
                #pragma unroll
                for (int j = 0; j < 4; j++)
                    mma_f16(acc[i][j], a[ks][i],
                            b[ks][j >> 1][(j & 1) * 2], b[ks][j >> 1][(j & 1) * 2 + 1]);
    }

    // fused epilogue
    const float S = 1.0f / 1024.f;
    int isKL = (bm >= 256);
    const float* L = isKL ? l1 : l0;
    int roff = isKL ? 256 : 0;
    float part = 0.f;
    #pragma unroll
    for (int i = 0; i < 2; i++) {
        int r0 = bm + wm + i * 16 + (lane >> 2);
        float lz0 = g_lZ[r0], lz1 = g_lZ[r0 + 8];
        const float* row0 = L + (size_t)(r0 - roff) * SS;
        const float* row1 = row0 + 8 * (size_t)SS;
        #pragma unroll
        for (int j = 0; j < 4; j++) {
            int col = bn + wn + j * 8 + (lane & 3) * 2;
            float2 p0 = *(const float2*)(row0 + col);
            float2 p1 = *(const float2*)(row1 + col);
            float v0 = acc[i][j][0] * S, v1 = acc[i][j][1] * S;
            float v2 = acc[i][j][2] * S, v3 = acc[i][j][3] * S;
            if (isKL) {
                part += v0 * (__logf(fmaxf(v0, 1e-12f)) - (p0.x - lz0));
                part += v1 * (__logf(fmaxf(v1, 1e-12f)) - (p0.y - lz0));
                part += v2 * (__logf(fmaxf(v2, 1e-12f)) - (p1.x - lz1));
                part += v3 * (__logf(fmaxf(v3, 1e-12f)) - (p1.y - lz1));
            } else {
                part += v0 * (p0.x - lz0) + v1 * (p0.y - lz0);
                part += v2 * (p1.x - lz1) + v3 * (p1.y - lz1);
            }
        }
    }
    part = bsum(part);
    if (tid == 0) atomicAdd(&g_acc[isKL ? 3 : 1], part);
}

__global__ void k_fin(float* __restrict__ out, const float* __restrict__ ramp) {
    if (threadIdx.x == 0) {
        const float invB = 1.0f / 256.0f;
        out[0] = g_acc[0] * invB;                                   // loss_nce
        out[1] = -(0.9f * g_acc[2] + 0.1f * g_acc[1]) * invB;       // loss_ce
        out[2] = ramp[0] * g_acc[3] * invB;                         // kl
    }
}

// momentum update of targeted rows (last occurrence wins). grid=BB, block=256
__global__ void k_upd(const float* __restrict__ f, const int* __restrict__ targets,
                      float* __restrict__ out) {
    int b = blockIdx.x, t = threadIdx.x;
    __shared__ int flag;
    int tb = targets[b];
    if (t == 0) {
        int ok = 1;
        for (int j = b + 1; j < BB; j++)
            if (targets[j] == tb) { ok = 0; break; }
        flag = ok;
    }
    __syncthreads();
    if (!flag) return;
    const float* fr = f   + (size_t)tb * FF;
    const float* xr = g_x + (size_t)b  * FF;
    float u[8];
    float s = 0.f;
    #pragma unroll
    for (int i = 0; i < 8; i++) {
        float v = 0.2f * fr[t + i * 256] + 0.8f * xr[t + i * 256];
        u[i] = v; s += v * v;
    }
    s = bsum(s);
    float inv = 1.f / fmaxf(sqrtf(s), 1e-12f);
    float* orow = out + (size_t)tb * FF;
    #pragma unroll
    for (int i = 0; i < 8; i++) orow[t + i * 256] = u[i] * inv;
}

extern "C" void kernel_launch(void* const* d_in, const int* in_sizes, int n_in,
                              void* d_out, int out_size) {
    const float* inputs0   = (const float*)d_in[0];
    const float* l0        = (const float*)d_in[1];
    const float* l1        = (const float*)d_in[2];
    const int*   targets   = (const int*)d_in[3];
    const int*   neighbors = (const int*)d_in[5];
    const float* ndist     = (const float*)d_in[6];
    const float* ramp      = (const float*)d_in[7];
    const float* feat      = (const float*)d_in[8];
    float* out = (float*)d_out;

    static cudaStream_t s1 = 0, s2 = 0;
    static cudaEvent_t e_norm = 0, e_c1 = 0, e_c2 = 0;
    static int inited = 0;
    if (!inited) {
        cudaFuncSetAttribute(k_gemm_mma, cudaFuncAttributeMaxDynamicSharedMemorySize,
                             4 * STAGE_B);
        cudaFuncSetAttribute(k_ngemm, cudaFuncAttributeMaxDynamicSharedMemorySize,
                             4 * STAGE2_B);
        cudaStreamCreateWithFlags(&s1, cudaStreamNonBlocking);
        cudaStreamCreateWithFlags(&s2, cudaStreamNonBlocking);
        cudaEventCreateWithFlags(&e_norm, cudaEventDisableTiming);
        cudaEventCreateWithFlags(&e_c1, cudaEventDisableTiming);
        cudaEventCreateWithFlags(&e_c2, cudaEventDisableTiming);
        inited = 1;
    }

    // chain1 head (also zeroes accumulators)
    k_norm<<<BB, 256>>>(inputs0);
    cudaEventRecord(e_norm, 0);

    // ---- fork chain3: feature copy + momentum update ----
    cudaStreamWaitEvent(s1, e_norm, 0);
    k_copy<<<2048, 256, 0, s1>>>(feat, out + 3);
    k_upd<<<BB, 256, 0, s1>>>(feat, targets, out + 3);
    cudaEventRecord(e_c1, s1);

    // ---- fork chain2: softmax stats -> W build -> neighbor GEMM (no transpose) ----
    cudaStreamWaitEvent(s2, e_norm, 0);
    dim3 gs(BB, 2);
    k_stats<<<gs, 256, 0, s2>>>(l0, l1);
    k_wbuild<<<BB, 256, 0, s2>>>(neighbors, ndist, targets, l0);
    dim3 gn(SS / 64, 4);
    k_ngemm<<<gn, 256, 4 * STAGE2_B, s2>>>(l0, l1);
    cudaEventRecord(e_c2, s2);

    // ---- chain1 continues on the main stream ----
    k_convB<<<SS, 256>>>(feat);
    dim3 gg(SS / 64, BB / 128);
    k_gemm_mma<<<gg, 256, 4 * STAGE_B>>>();
    k_nce2<<<BB, 256>>>(targets, feat);

    // join and finalize
    cudaStreamWaitEvent(0, e_c1, 0);
    cudaStreamWaitEvent(0, e_c2, 0);
    k_fin<<<1, 32>>>(out, ramp);
}